// round 14
// baseline (speedup 1.0000x reference)
#include <cuda_runtime.h>
#include <cuda_fp16.h>
#include <cstdint>

// ---------------------------------------------------------------------------
// MoE top-1: router -> gather -> fp16 m16n8k16 GEMMs fed by cp.async 3-stage
// pipeline over PRE-PACKED fp16 operands (Wp k-pair packed, Xgh/Hgh rowwise).
// Per-stage checkers; PROVEN tf32 GEMMs (R12) re-run any failed stage.
// ---------------------------------------------------------------------------

#define T_TOK   16384
#define DM      1024
#define DFF     4096
#define NE      8
#define BM      128
#define BN      128
#define BKH     64              // fp16 cp.async path: K per stage
#define LDHA    72              // sA row stride in halves (64 data + 8 pad)
#define LDBP    136             // sBp row stride in uint32 (128 data + 8 pad)
#define NSTG    3
#define A_BYTES (BM * LDHA * 2)             // 18432
#define B_BYTES ((BKH / 2) * LDBP * 4)      // 17408
#define STG     (A_BYTES + B_BYTES)         // 35840
#define SMEM_CP (NSTG * STG)                // 107520
#define BK      16              // tf32 fallback K per stage
#define LDA     20
#define LDB     136
#define MAX_MT  136
#define PADCAP  (MAX_MT * BM)

// ------------------------------- scratch -----------------------------------
__device__ float    g_Xg32[(size_t)PADCAP * DM];
__device__ float    g_Hg32[(size_t)PADCAP * DFF];
__device__ __half   g_Xgh[(size_t)PADCAP * DM];
__device__ __half   g_Hgh[(size_t)PADCAP * DFF];
__device__ uint32_t g_W1p[(size_t)NE * (DM / 2) * DFF];   // [e][kpair][n]
__device__ uint32_t g_W2p[(size_t)NE * (DFF / 2) * DM];
__device__ int   g_expert[T_TOK];
__device__ float g_wtok[T_TOK];
__device__ int   g_counts[NE];
__device__ int   g_cursor[NE];
__device__ int   g_segstart[NE];
__device__ int   g_pos[T_TOK];
__device__ int   g_gtok[PADCAP];
__device__ int   g_tile_e[MAX_MT];
__device__ int   g_tile_m0[MAX_MT];
__device__ int   g_fb1, g_fb2, g_viol1, g_viol2, g_code;
__device__ float g_sink;

#define MMA16816(d, a, b) \
    asm volatile("mma.sync.aligned.m16n8k16.row.col.f32.f16.f16.f32 " \
                 "{%0,%1,%2,%3}, {%4,%5,%6,%7}, {%8,%9}, {%0,%1,%2,%3};" \
                 : "+f"((d)[0]), "+f"((d)[1]), "+f"((d)[2]), "+f"((d)[3]) \
                 : "r"((a)[0]), "r"((a)[1]), "r"((a)[2]), "r"((a)[3]), \
                   "r"((b)[0]), "r"((b)[1]))

#define MMATF32(d, a, b) \
    asm volatile("mma.sync.aligned.m16n8k8.row.col.f32.tf32.tf32.f32 " \
                 "{%0,%1,%2,%3}, {%4,%5,%6,%7}, {%8,%9}, {%0,%1,%2,%3};" \
                 : "+f"((d)[0]), "+f"((d)[1]), "+f"((d)[2]), "+f"((d)[3]) \
                 : "r"((a)[0]), "r"((a)[1]), "r"((a)[2]), "r"((a)[3]), \
                   "r"((b)[0]), "r"((b)[1]))

__device__ __forceinline__ uint32_t f2tf32(float f) {
    uint32_t r;
    asm("cvt.rna.tf32.f32 %0, %1;" : "=r"(r) : "f"(f));
    return r;
}
__device__ __forceinline__ uint4 cvt4(float4 v) {
    uint4 o;
    o.x = f2tf32(v.x); o.y = f2tf32(v.y);
    o.z = f2tf32(v.z); o.w = f2tf32(v.w);
    return o;
}
__device__ __forceinline__ uint32_t h2u(__half2 h) { return *(uint32_t*)&h; }
__device__ __forceinline__ uint32_t smem_u32(const void* p) {
    uint32_t a;
    asm("{ .reg .u64 t; cvta.to.shared.u64 t, %1; cvt.u32.u64 %0, t; }"
        : "=r"(a) : "l"(p));
    return a;
}
__device__ __forceinline__ void cp16(uint32_t dst, const void* src) {
    asm volatile("cp.async.cg.shared.global [%0], [%1], 16;"
                 :: "r"(dst), "l"(src) : "memory");
}
__device__ __forceinline__ void cp_commit() {
    asm volatile("cp.async.commit_group;" ::: "memory");
}
template <int N> __device__ __forceinline__ void cp_wait() {
    asm volatile("cp.async.wait_group %0;" :: "n"(N) : "memory");
}

// ------------------------------- front end ---------------------------------

__global__ void init_kernel() {
    if (threadIdx.x < NE) g_counts[threadIdx.x] = 0;
    if (threadIdx.x == 0) { g_viol1 = 0; g_viol2 = 0; }
}

__global__ void router_kernel(const float* __restrict__ x,
                              const float* __restrict__ Wr,
                              const float* __restrict__ br) {
    int warp = (blockIdx.x * blockDim.x + threadIdx.x) >> 5;
    int lane = threadIdx.x & 31;
    if (warp >= T_TOK) return;
    const float* xr = x + (size_t)warp * DM;
    float acc[NE];
#pragma unroll
    for (int e = 0; e < NE; e++) acc[e] = 0.f;
    for (int i = lane; i < DM; i += 32) {
        float xv = xr[i];
        const float* w = Wr + (size_t)i * NE;
#pragma unroll
        for (int e = 0; e < NE; e++) acc[e] = fmaf(xv, w[e], acc[e]);
    }
#pragma unroll
    for (int off = 16; off; off >>= 1)
#pragma unroll
        for (int e = 0; e < NE; e++)
            acc[e] += __shfl_xor_sync(0xffffffffu, acc[e], off);
    if (lane == 0) {
        float m = -1e30f; int be = 0;
#pragma unroll
        for (int e = 0; e < NE; e++) {
            float l = acc[e] + br[e];
            acc[e] = l;
            if (l > m) { m = l; be = e; }
        }
        float s = 0.f;
#pragma unroll
        for (int e = 0; e < NE; e++) s += expf(acc[e] - m);
        g_expert[warp] = be;
        g_wtok[warp]   = 1.0f / s;
        atomicAdd(&g_counts[be], 1);
    }
}

__global__ void plan_kernel() {
    if (threadIdx.x != 0) return;
    int off = 0, nt = 0;
    for (int e = 0; e < NE; e++) {
        g_segstart[e] = off;
        g_cursor[e]   = off;
        int c = g_counts[e];
        int ntile = (c + BM - 1) / BM;
        for (int i = 0; i < ntile; i++) {
            g_tile_e[nt]  = e;
            g_tile_m0[nt] = off + i * BM;
            nt++;
        }
        off += ntile * BM;
    }
    for (int i = nt; i < MAX_MT; i++) g_tile_e[i] = -1;
}

__global__ void scatter_pos_kernel() {
    int t = blockIdx.x * blockDim.x + threadIdx.x;
    if (t >= T_TOK) return;
    int e = g_expert[t];
    int p = atomicAdd(&g_cursor[e], 1);
    g_pos[t] = p;
    g_gtok[p] = t;
}

__global__ void gather_x_kernel(const float* __restrict__ x) {
    int t = blockIdx.x;
    int p = g_pos[t];
    const float4* src = (const float4*)(x + (size_t)t * DM);
    float4* d32 = (float4*)(g_Xg32 + (size_t)p * DM);
    __half2* d16 = (__half2*)(g_Xgh + (size_t)p * DM);
    for (int i = threadIdx.x; i < DM / 4; i += blockDim.x) {
        float4 v = src[i];
        d32[i] = v;
        d16[2 * i]     = __floats2half2_rn(v.x, v.y);
        d16[2 * i + 1] = __floats2half2_rn(v.z, v.w);
    }
}

__global__ void zero_pad_kernel() {
    for (int e = 0; e < NE; e++) {
        int s0 = g_segstart[e], c = g_counts[e];
        int pad_end = s0 + ((c + BM - 1) / BM) * BM;
        for (int r = s0 + c + blockIdx.x; r < pad_end; r += gridDim.x) {
            float4* d32 = (float4*)(g_Xg32 + (size_t)r * DM);
            float2* d16 = (float2*)(g_Xgh + (size_t)r * DM);
            for (int i = threadIdx.x; i < DM / 4; i += blockDim.x) {
                d32[i] = make_float4(0.f, 0.f, 0.f, 0.f);
                d16[i] = make_float2(0.f, 0.f);
            }
        }
    }
}

// Pack W [e][K][N] fp32 -> Wp [e][K/2][N] uint32(half2{W[2p][n],W[2p+1][n]})
__global__ void pack_w_kernel(const float* __restrict__ W,
                              uint32_t* __restrict__ Wp, int K, int N) {
    int e = blockIdx.z;
    int p = blockIdx.y;
    int n = (blockIdx.x * blockDim.x + threadIdx.x) * 4;
    if (n >= N) return;
    const float* base = W + (size_t)e * K * N;
    float4 r0 = *(const float4*)(base + (size_t)(2 * p) * N + n);
    float4 r1 = *(const float4*)(base + (size_t)(2 * p + 1) * N + n);
    uint4 v;
    v.x = h2u(__floats2half2_rn(r0.x, r1.x));
    v.y = h2u(__floats2half2_rn(r0.y, r1.y));
    v.z = h2u(__floats2half2_rn(r0.z, r1.z));
    v.w = h2u(__floats2half2_rn(r0.w, r1.w));
    *(uint4*)(Wp + (size_t)e * (K / 2) * N + (size_t)p * N + n) = v;
}

// ----------------- fp16 cp.async grouped GEMM (fast path) ------------------
// A: fp16 [rows][KTOT] (Xgh or Hgh). B: Wp packed [e][KTOT/2][NTOT].
// MODE 1: Hgh/Hg32 = relu(A@W1 + b1).  MODE 2: out = (A@W2 + b2) * wtok.
template <int KTOT, int NTOT, int MODE>
__global__ __launch_bounds__(256)
void moe_gemm_f16cp(const uint32_t* __restrict__ Wp,
                    const float* __restrict__ bias, float* __restrict__ outp) {
    int ti = blockIdx.y;
    int e  = g_tile_e[ti];
    if (e < 0) return;
    int m0 = g_tile_m0[ti];
    int n0 = blockIdx.x * BN;

    extern __shared__ char smem[];
    uint32_t sb = smem_u32(smem);

    int tid = threadIdx.x, lane = tid & 31, wid = tid >> 5;
    int wm = (wid & 3) * 32;       // 4 warps in M: 2 x m16 tiles
    int wn = (wid >> 2) * 64;      // 2 warps in N: 8 x n8 tiles

    const __half*   Agl = ((MODE == 1) ? g_Xgh : g_Hgh) + (size_t)m0 * KTOT;
    const uint32_t* Bgl = Wp + (size_t)e * (KTOT / 2) * NTOT + n0;
    const int NKB = KTOT / BKH;

    float acc[2][8][4];
#pragma unroll
    for (int i = 0; i < 2; i++)
#pragma unroll
        for (int j = 0; j < 8; j++)
#pragma unroll
            for (int q = 0; q < 4; q++) acc[i][j][q] = 0.f;

    // cp slots: A 128 rows x 8 chunks (16B) = 1024; B 32 prow x 32 chunks = 1024
    int ar[4], ac[4], bp[4], bc[4];
#pragma unroll
    for (int j = 0; j < 4; j++) {
        int u = j * 256 + tid;
        ar[j] = u >> 3;  ac[j] = u & 7;
        bp[j] = u >> 5;  bc[j] = u & 31;
    }

    auto load_stage = [&](int slot, int kb) {
        uint32_t sA = sb + slot * STG;
        uint32_t sB = sA + A_BYTES;
        const __half*   As = Agl + kb * BKH;
        const uint32_t* Bs = Bgl + (size_t)(kb * (BKH / 2)) * NTOT;
#pragma unroll
        for (int j = 0; j < 4; j++)
            cp16(sA + ar[j] * (LDHA * 2) + ac[j] * 16,
                 As + (size_t)ar[j] * KTOT + ac[j] * 8);
#pragma unroll
        for (int j = 0; j < 4; j++)
            cp16(sB + bp[j] * (LDBP * 4) + bc[j] * 16,
                 Bs + (size_t)bp[j] * NTOT + bc[j] * 4);
    };

    load_stage(0, 0); cp_commit();
    load_stage(1, 1); cp_commit();

    const int fr = lane >> 2;          // 0..7
    const int fk = lane & 3;           // 0..3

    int slot = 0;
    for (int kb = 0; kb < NKB; kb++) {
        cp_wait<1>();
        __syncthreads();
        if (kb + 2 < NKB) load_stage((slot + 2) % NSTG, kb + 2);
        cp_commit();

        const __half*   cA = (const __half*)(smem + slot * STG);
        const uint32_t* cB = (const uint32_t*)(smem + slot * STG + A_BYTES);
#pragma unroll
        for (int kk = 0; kk < 4; kk++) {           // 4 x k16 per BKH=64
            uint32_t a[2][4];
#pragma unroll
            for (int mt = 0; mt < 2; mt++) {
                const __half* pA = cA + (wm + mt * 16 + fr) * LDHA + 16 * kk + 2 * fk;
                a[mt][0] = *(const uint32_t*)(pA);
                a[mt][1] = *(const uint32_t*)(pA + 8 * LDHA);
                a[mt][2] = *(const uint32_t*)(pA + 8);
                a[mt][3] = *(const uint32_t*)(pA + 8 * LDHA + 8);
            }
            uint32_t b[8][2];
#pragma unroll
            for (int nf = 0; nf < 8; nf++) {
                int n = wn + nf * 8 + fr;
                b[nf][0] = cB[(8 * kk + fk) * LDBP + n];
                b[nf][1] = cB[(8 * kk + fk + 4) * LDBP + n];
            }
#pragma unroll
            for (int mt = 0; mt < 2; mt++)
#pragma unroll
                for (int nf = 0; nf < 8; nf++)
                    MMA16816(acc[mt][nf], a[mt], b[nf]);
        }
        __syncthreads();
        slot = (slot + 1) % NSTG;
    }

    // ------------------------------ epilogue -------------------------------
    if (MODE == 1) {
        const float* bg = bias + (size_t)e * DFF + n0;
#pragma unroll
        for (int mt = 0; mt < 2; mt++) {
            int rg = m0 + wm + mt * 16 + fr;
#pragma unroll
            for (int nf = 0; nf < 8; nf++) {
                int col = wn + nf * 8 + 2 * fk;
                float b0 = bg[col], b1 = bg[col + 1];
                float v0 = fmaxf(acc[mt][nf][0] + b0, 0.f);
                float v1 = fmaxf(acc[mt][nf][1] + b1, 0.f);
                float v2 = fmaxf(acc[mt][nf][2] + b0, 0.f);
                float v3 = fmaxf(acc[mt][nf][3] + b1, 0.f);
                *(float2*)(g_Hg32 + (size_t)rg * DFF + n0 + col) =
                    make_float2(v0, v1);
                *(float2*)(g_Hg32 + (size_t)(rg + 8) * DFF + n0 + col) =
                    make_float2(v2, v3);
                *(uint32_t*)(g_Hgh + (size_t)rg * DFF + n0 + col) =
                    h2u(__floats2half2_rn(v0, v1));
                *(uint32_t*)(g_Hgh + (size_t)(rg + 8) * DFF + n0 + col) =
                    h2u(__floats2half2_rn(v2, v3));
            }
        }
    } else {
        const float* bg = bias + (size_t)e * DM + n0;
        int seg0 = g_segstart[e], cnt = g_counts[e];
#pragma unroll
        for (int mt = 0; mt < 2; mt++) {
#pragma unroll
            for (int h = 0; h < 2; h++) {
                int gr = m0 + wm + mt * 16 + fr + h * 8;
                if ((gr - seg0) < cnt) {
                    int tok = g_gtok[gr];
                    float w = g_wtok[tok];
                    float* orow = outp + (size_t)tok * DM + n0;
#pragma unroll
                    for (int nf = 0; nf < 8; nf++) {
                        int col = wn + nf * 8 + 2 * fk;
                        *(float2*)(orow + col) =
                            make_float2((acc[mt][nf][2 * h]     + bg[col])     * w,
                                        (acc[mt][nf][2 * h + 1] + bg[col + 1]) * w);
                    }
                }
            }
        }
    }
}

// --------------------------- checkers + arbitration ------------------------
__global__ __launch_bounds__(512)
void check1_kernel(const float* __restrict__ x,  const float* __restrict__ W1,
                   const float* __restrict__ b1) {
    __shared__ float h[DFF];
    int t = 3 + blockIdx.x * 8190;
    int e = g_expert[t];
    int p = g_pos[t];
    const float* xr = x + (size_t)t * DM;
    const float* w1 = W1 + (size_t)e * DM * DFF;
    for (int n = threadIdx.x; n < DFF; n += 512) {
        float acc = b1[(size_t)e * DFF + n];
        for (int k = 0; k < DM; k++)
            acc = fmaf(xr[k], w1[(size_t)k * DFF + n], acc);
        h[n] = fmaxf(acc, 0.f);
    }
    __syncthreads();
    int viol = 0;
    for (int n = threadIdx.x; n < DFF; n += 512) {
        float got = g_Hg32[(size_t)p * DFF + n];
        if (fabsf(got - h[n]) > 0.03f + 0.03f * fabsf(h[n])) viol++;
    }
    if (viol) atomicAdd(&g_viol1, viol);
}

__global__ __launch_bounds__(512)
void check2_kernel(const float* __restrict__ x,  const float* __restrict__ W1,
                   const float* __restrict__ b1, const float* __restrict__ W2,
                   const float* __restrict__ b2, const float* __restrict__ outp) {
    __shared__ float h[DFF];
    int t = 1 + blockIdx.x * 4099;
    int e = g_expert[t];
    float w = g_wtok[t];
    const float* xr = x + (size_t)t * DM;
    const float* w1 = W1 + (size_t)e * DM * DFF;
    const float* w2 = W2 + (size_t)e * DFF * DM;
    for (int n = threadIdx.x; n < DFF; n += 512) {
        float acc = b1[(size_t)e * DFF + n];
        for (int k = 0; k < DM; k++)
            acc = fmaf(xr[k], w1[(size_t)k * DFF + n], acc);
        h[n] = fmaxf(acc, 0.f);
    }
    __syncthreads();
    int viol = 0;
    for (int n = threadIdx.x; n < DM; n += 512) {
        float acc = b2[(size_t)e * DM + n];
        for (int k = 0; k < DFF; k++)
            acc = fmaf(h[k], w2[(size_t)k * DM + n], acc);
        float ref = acc * w;
        float got = outp[(size_t)t * DM + n];
        if (fabsf(got - ref) > 0.03f + 0.03f * fabsf(ref)) viol++;
    }
    if (viol) atomicAdd(&g_viol2, viol);
}

__global__ void setfb_kernel() {
    if (threadIdx.x == 0) {
        int c1 = (g_viol1 > 96), c2 = (g_viol2 > 128);
        g_fb1  = c1;
        g_fb2  = c1 || c2;
        g_code = c1 + 2 * c2;
    }
}

__global__ void spin_kernel() {
    int code = g_code;
    if (!code) return;
    long long t0 = clock64();
    long long lim = (long long)code * 1500000LL;
    long long acc = 0;
    while (clock64() - t0 < lim) acc++;
    if (acc == -1) g_sink = 1.f;
}

// ----------------------- tf32 mma GEMM (PROVEN fallback) -------------------
template <int KTOT, int NTOT, int MODE>
__global__ __launch_bounds__(256)
void moe_gemm_tf32(const float* __restrict__ W, const float* __restrict__ bias,
                   float* __restrict__ outp) {
    if (MODE == 1 ? !g_fb1 : !g_fb2) return;
    int ti = blockIdx.y;
    int e  = g_tile_e[ti];
    if (e < 0) return;
    int m0 = g_tile_m0[ti];
    int n0 = blockIdx.x * BN;

    __shared__ alignas(16) float sA[2][BM][LDA];
    __shared__ alignas(16) float sB[2][BK][LDB];

    int tid = threadIdx.x, lane = tid & 31, wid = tid >> 5;
    int wm = (wid & 3) * 32;
    int wn = (wid >> 2) * 64;

    const float* Agl = ((MODE == 1) ? g_Xg32 : g_Hg32) + (size_t)m0 * KTOT;
    const float* Bgl = W + (size_t)e * KTOT * NTOT + n0;
    const int NKB = KTOT / BK;

    float acc[2][8][4];
#pragma unroll
    for (int i = 0; i < 2; i++)
#pragma unroll
        for (int j = 0; j < 8; j++)
#pragma unroll
            for (int q = 0; q < 4; q++) acc[i][j][q] = 0.f;

    int ra[2], ca[2], rb[2], cb[2];
#pragma unroll
    for (int j = 0; j < 2; j++) {
        int idx = j * 256 + tid;
        ra[j] = idx >> 2;  ca[j] = idx & 3;
        rb[j] = idx >> 5;  cb[j] = idx & 31;
    }

    float4 pa[2], pb[2];
    auto ldg = [&](int kb) {
        const float* An = Agl + kb * BK;
        const float* Bn = Bgl + (size_t)kb * BK * NTOT;
#pragma unroll
        for (int j = 0; j < 2; j++) {
            pa[j] = *(const float4*)(An + (size_t)ra[j] * KTOT + ca[j] * 4);
            pb[j] = *(const float4*)(Bn + (size_t)rb[j] * NTOT + cb[j] * 4);
        }
    };
    auto sts = [&](int s) {
#pragma unroll
        for (int j = 0; j < 2; j++) {
            *(uint4*)&sA[s][ra[j]][ca[j] * 4] = cvt4(pa[j]);
            *(uint4*)&sB[s][rb[j]][cb[j] * 4] = cvt4(pb[j]);
        }
    };

    ldg(0); sts(0);
    __syncthreads();

    const int fr = lane >> 2;
    const int fk = lane & 3;

    for (int kb = 0; kb < NKB; kb++) {
        if (kb + 1 < NKB) ldg(kb + 1);
        int s = kb & 1;
#pragma unroll
        for (int kk = 0; kk < 2; kk++) {
            int k0 = kk * 8;
            uint32_t a[2][4];
#pragma unroll
            for (int mt = 0; mt < 2; mt++) {
                const float* pA = &sA[s][wm + mt * 16 + fr][k0 + fk];
                a[mt][0] = *(const uint32_t*)(pA);
                a[mt][1] = *(const uint32_t*)(pA + 8 * LDA);
                a[mt][2] = *(const uint32_t*)(pA + 4);
                a[mt][3] = *(const uint32_t*)(pA + 8 * LDA + 4);
            }
            uint32_t b[8][2];
#pragma unroll
            for (int nf = 0; nf < 8; nf++) {
                const float* pB = &sB[s][k0 + fk][wn + nf * 8 + fr];
                b[nf][0] = *(const uint32_t*)(pB);
                b[nf][1] = *(const uint32_t*)(pB + 4 * LDB);
            }
#pragma unroll
            for (int mt = 0; mt < 2; mt++)
#pragma unroll
                for (int nf = 0; nf < 8; nf++)
                    MMATF32(acc[mt][nf], a[mt], b[nf]);
        }
        __syncthreads();
        if (kb + 1 < NKB) {
            sts((kb + 1) & 1);
            __syncthreads();
        }
    }

    if (MODE == 1) {
        const float* bg = bias + (size_t)e * DFF + n0;
#pragma unroll
        for (int mt = 0; mt < 2; mt++) {
            int rg = m0 + wm + mt * 16 + fr;
#pragma unroll
            for (int nf = 0; nf < 8; nf++) {
                int col = wn + nf * 8 + 2 * fk;
                float b0 = bg[col], b1 = bg[col + 1];
                *(float2*)(g_Hg32 + (size_t)rg * DFF + n0 + col) =
                    make_float2(fmaxf(acc[mt][nf][0] + b0, 0.f),
                                fmaxf(acc[mt][nf][1] + b1, 0.f));
                *(float2*)(g_Hg32 + (size_t)(rg + 8) * DFF + n0 + col) =
                    make_float2(fmaxf(acc[mt][nf][2] + b0, 0.f),
                                fmaxf(acc[mt][nf][3] + b1, 0.f));
            }
        }
    } else {
        const float* bg = bias + (size_t)e * DM + n0;
        int seg0 = g_segstart[e], cnt = g_counts[e];
#pragma unroll
        for (int mt = 0; mt < 2; mt++) {
#pragma unroll
            for (int h = 0; h < 2; h++) {
                int gr = m0 + wm + mt * 16 + fr + h * 8;
                if ((gr - seg0) < cnt) {
                    int tok = g_gtok[gr];
                    float w = g_wtok[tok];
                    float* orow = outp + (size_t)tok * DM + n0;
#pragma unroll
                    for (int nf = 0; nf < 8; nf++) {
                        int col = wn + nf * 8 + 2 * fk;
                        *(float2*)(orow + col) =
                            make_float2((acc[mt][nf][2 * h]     + bg[col])     * w,
                                        (acc[mt][nf][2 * h + 1] + bg[col + 1]) * w);
                    }
                }
            }
        }
    }
}

// ------------------------------ launcher -----------------------------------
extern "C" void kernel_launch(void* const* d_in, const int* in_sizes, int n_in,
                              void* d_out, int out_size) {
    const float* x  = (const float*)d_in[0];
    const float* Wr = (const float*)d_in[1];
    const float* br = (const float*)d_in[2];
    const float* W1 = (const float*)d_in[3];
    const float* b1 = (const float*)d_in[4];
    const float* W2 = (const float*)d_in[5];
    const float* b2 = (const float*)d_in[6];
    float* out = (float*)d_out;
    (void)in_sizes; (void)n_in; (void)out_size;

    init_kernel<<<1, 32>>>();
    router_kernel<<<T_TOK / 8, 256>>>(x, Wr, br);
    plan_kernel<<<1, 32>>>();
    scatter_pos_kernel<<<T_TOK / 256, 256>>>();
    gather_x_kernel<<<T_TOK, 128>>>(x);
    zero_pad_kernel<<<64, 128>>>();

    // pack weights to fp16 k-pair layout (native n-order, no transpose)
    pack_w_kernel<<<dim3(DFF / 1024, DM / 2, NE), 256>>>(W1, g_W1p, DM, DFF);
    pack_w_kernel<<<dim3(1, DFF / 2, NE), 256>>>(W2, g_W2p, DFF, DM);

    cudaFuncSetAttribute(moe_gemm_f16cp<DM, DFF, 1>,
                         cudaFuncAttributeMaxDynamicSharedMemorySize, SMEM_CP);
    cudaFuncSetAttribute(moe_gemm_f16cp<DFF, DM, 2>,
                         cudaFuncAttributeMaxDynamicSharedMemorySize, SMEM_CP);

    moe_gemm_f16cp<DM, DFF, 1><<<dim3(DFF / BN, MAX_MT), 256, SMEM_CP>>>(g_W1p, b1, nullptr);
    check1_kernel<<<2, 512>>>(x, W1, b1);
    moe_gemm_f16cp<DFF, DM, 2><<<dim3(DM / BN, MAX_MT), 256, SMEM_CP>>>(g_W2p, b2, out);
    check2_kernel<<<4, 512>>>(x, W1, b1, W2, b2, out);
    setfb_kernel<<<1, 32>>>();
    spin_kernel<<<1, 32>>>();

    // PROVEN tf32 fallback, per stage (skips in ~20us when fp16 verified OK)
    moe_gemm_tf32<DM, DFF, 1><<<dim3(DFF / BN, MAX_MT), 256>>>(W1, b1, nullptr);
    moe_gemm_tf32<DFF, DM, 2><<<dim3(DM / BN, MAX_MT), 256>>>(W2, b2, out);
}

// round 15
// speedup vs baseline: 1.0988x; 1.0988x over previous
#include <cuda_runtime.h>
#include <cuda_fp16.h>
#include <cstdint>

// ---------------------------------------------------------------------------
// MoE top-1: router -> gather -> fp16 m16n8k16 GEMMs using the PROVEN R13
// mainloop (2-stage LDG->reg->STS double buffer) fed by PRE-PACKED fp16
// operands (halved global traffic, no in-loop conversion).
// Per-stage checkers; PROVEN tf32 GEMMs re-run any failed stage.
// ---------------------------------------------------------------------------

#define T_TOK   16384
#define DM      1024
#define DFF     4096
#define NE      8
#define BM      128
#define BN      128
#define BKH     32              // fp16 path K per stage (as R13)
#define LDHA    40              // sA row stride in halves (as R13)
#define LDBP    136             // sBp row stride in uint32 (as R13)
#define BK      16              // tf32 fallback K per stage
#define LDA     20
#define LDB     136
#define MAX_MT  136
#define PADCAP  (MAX_MT * BM)

// ------------------------------- scratch -----------------------------------
__device__ float    g_Xg32[(size_t)PADCAP * DM];
__device__ float    g_Hg32[(size_t)PADCAP * DFF];
__device__ __half   g_Xgh[(size_t)PADCAP * DM];
__device__ __half   g_Hgh[(size_t)PADCAP * DFF];
__device__ uint32_t g_W1p[(size_t)NE * (DM / 2) * DFF];   // [e][kpair][n]
__device__ uint32_t g_W2p[(size_t)NE * (DFF / 2) * DM];
__device__ int   g_expert[T_TOK];
__device__ float g_wtok[T_TOK];
__device__ int   g_counts[NE];
__device__ int   g_cursor[NE];
__device__ int   g_segstart[NE];
__device__ int   g_pos[T_TOK];
__device__ int   g_gtok[PADCAP];
__device__ int   g_tile_e[MAX_MT];
__device__ int   g_tile_m0[MAX_MT];
__device__ int   g_fb1, g_fb2, g_viol1, g_viol2, g_code;
__device__ float g_sink;

#define MMA16816(d, a, b) \
    asm volatile("mma.sync.aligned.m16n8k16.row.col.f32.f16.f16.f32 " \
                 "{%0,%1,%2,%3}, {%4,%5,%6,%7}, {%8,%9}, {%0,%1,%2,%3};" \
                 : "+f"((d)[0]), "+f"((d)[1]), "+f"((d)[2]), "+f"((d)[3]) \
                 : "r"((a)[0]), "r"((a)[1]), "r"((a)[2]), "r"((a)[3]), \
                   "r"((b)[0]), "r"((b)[1]))

#define MMATF32(d, a, b) \
    asm volatile("mma.sync.aligned.m16n8k8.row.col.f32.tf32.tf32.f32 " \
                 "{%0,%1,%2,%3}, {%4,%5,%6,%7}, {%8,%9}, {%0,%1,%2,%3};" \
                 : "+f"((d)[0]), "+f"((d)[1]), "+f"((d)[2]), "+f"((d)[3]) \
                 : "r"((a)[0]), "r"((a)[1]), "r"((a)[2]), "r"((a)[3]), \
                   "r"((b)[0]), "r"((b)[1]))

__device__ __forceinline__ uint32_t f2tf32(float f) {
    uint32_t r;
    asm("cvt.rna.tf32.f32 %0, %1;" : "=r"(r) : "f"(f));
    return r;
}
__device__ __forceinline__ uint4 cvt4(float4 v) {
    uint4 o;
    o.x = f2tf32(v.x); o.y = f2tf32(v.y);
    o.z = f2tf32(v.z); o.w = f2tf32(v.w);
    return o;
}
__device__ __forceinline__ uint32_t h2u(__half2 h) { return *(uint32_t*)&h; }

// ------------------------------- front end ---------------------------------

__global__ void init_kernel() {
    if (threadIdx.x < NE) g_counts[threadIdx.x] = 0;
    if (threadIdx.x == 0) { g_viol1 = 0; g_viol2 = 0; }
}

__global__ void router_kernel(const float* __restrict__ x,
                              const float* __restrict__ Wr,
                              const float* __restrict__ br) {
    int warp = (blockIdx.x * blockDim.x + threadIdx.x) >> 5;
    int lane = threadIdx.x & 31;
    if (warp >= T_TOK) return;
    const float* xr = x + (size_t)warp * DM;
    float acc[NE];
#pragma unroll
    for (int e = 0; e < NE; e++) acc[e] = 0.f;
    for (int i = lane; i < DM; i += 32) {
        float xv = xr[i];
        const float* w = Wr + (size_t)i * NE;
#pragma unroll
        for (int e = 0; e < NE; e++) acc[e] = fmaf(xv, w[e], acc[e]);
    }
#pragma unroll
    for (int off = 16; off; off >>= 1)
#pragma unroll
        for (int e = 0; e < NE; e++)
            acc[e] += __shfl_xor_sync(0xffffffffu, acc[e], off);
    if (lane == 0) {
        float m = -1e30f; int be = 0;
#pragma unroll
        for (int e = 0; e < NE; e++) {
            float l = acc[e] + br[e];
            acc[e] = l;
            if (l > m) { m = l; be = e; }
        }
        float s = 0.f;
#pragma unroll
        for (int e = 0; e < NE; e++) s += expf(acc[e] - m);
        g_expert[warp] = be;
        g_wtok[warp]   = 1.0f / s;
        atomicAdd(&g_counts[be], 1);
    }
}

__global__ void plan_kernel() {
    if (threadIdx.x != 0) return;
    int off = 0, nt = 0;
    for (int e = 0; e < NE; e++) {
        g_segstart[e] = off;
        g_cursor[e]   = off;
        int c = g_counts[e];
        int ntile = (c + BM - 1) / BM;
        for (int i = 0; i < ntile; i++) {
            g_tile_e[nt]  = e;
            g_tile_m0[nt] = off + i * BM;
            nt++;
        }
        off += ntile * BM;
    }
    for (int i = nt; i < MAX_MT; i++) g_tile_e[i] = -1;
}

__global__ void scatter_pos_kernel() {
    int t = blockIdx.x * blockDim.x + threadIdx.x;
    if (t >= T_TOK) return;
    int e = g_expert[t];
    int p = atomicAdd(&g_cursor[e], 1);
    g_pos[t] = p;
    g_gtok[p] = t;
}

__global__ void gather_x_kernel(const float* __restrict__ x) {
    int t = blockIdx.x;
    int p = g_pos[t];
    const float4* src = (const float4*)(x + (size_t)t * DM);
    float4* d32 = (float4*)(g_Xg32 + (size_t)p * DM);
    __half2* d16 = (__half2*)(g_Xgh + (size_t)p * DM);
    for (int i = threadIdx.x; i < DM / 4; i += blockDim.x) {
        float4 v = src[i];
        d32[i] = v;
        d16[2 * i]     = __floats2half2_rn(v.x, v.y);
        d16[2 * i + 1] = __floats2half2_rn(v.z, v.w);
    }
}

__global__ void zero_pad_kernel() {
    for (int e = 0; e < NE; e++) {
        int s0 = g_segstart[e], c = g_counts[e];
        int pad_end = s0 + ((c + BM - 1) / BM) * BM;
        for (int r = s0 + c + blockIdx.x; r < pad_end; r += gridDim.x) {
            float4* d32 = (float4*)(g_Xg32 + (size_t)r * DM);
            float2* d16 = (float2*)(g_Xgh + (size_t)r * DM);
            for (int i = threadIdx.x; i < DM / 4; i += blockDim.x) {
                d32[i] = make_float4(0.f, 0.f, 0.f, 0.f);
                d16[i] = make_float2(0.f, 0.f);
            }
        }
    }
}

// Pack W [e][K][N] fp32 -> Wp [e][K/2][N] uint32(half2{W[2p][n],W[2p+1][n]})
__global__ void pack_w_kernel(const float* __restrict__ W,
                              uint32_t* __restrict__ Wp, int K, int N) {
    int e = blockIdx.z;
    int p = blockIdx.y;
    int n = (blockIdx.x * blockDim.x + threadIdx.x) * 4;
    if (n >= N) return;
    const float* base = W + (size_t)e * K * N;
    float4 r0 = *(const float4*)(base + (size_t)(2 * p) * N + n);
    float4 r1 = *(const float4*)(base + (size_t)(2 * p + 1) * N + n);
    uint4 v;
    v.x = h2u(__floats2half2_rn(r0.x, r1.x));
    v.y = h2u(__floats2half2_rn(r0.y, r1.y));
    v.z = h2u(__floats2half2_rn(r0.z, r1.z));
    v.w = h2u(__floats2half2_rn(r0.w, r1.w));
    *(uint4*)(Wp + (size_t)e * (K / 2) * N + (size_t)p * N + n) = v;
}

// ----------------------- fp16 mma grouped GEMM (R13 structure) -------------
// A: fp16 [rows][KTOT] (Xgh or Hgh). B: Wp packed [e][KTOT/2][NTOT].
// MODE 1: Hgh/Hg32 = relu(A@W1 + b1).  MODE 2: out = (A@W2 + b2) * wtok.
template <int KTOT, int NTOT, int MODE>
__global__ __launch_bounds__(256)
void moe_gemm_f16(const uint32_t* __restrict__ Wp,
                  const float* __restrict__ bias, float* __restrict__ outp) {
    int ti = blockIdx.y;
    int e  = g_tile_e[ti];
    if (e < 0) return;
    int m0 = g_tile_m0[ti];
    int n0 = blockIdx.x * BN;

    __shared__ alignas(16) __half   sA[2][BM][LDHA];        // [m][k] halves
    __shared__ alignas(16) uint32_t sBp[2][BKH / 2][LDBP];  // [kpair][n] half2

    int tid = threadIdx.x, lane = tid & 31, wid = tid >> 5;
    int wm = (wid & 3) * 32;       // 4 warps in M: 2 x m16 tiles
    int wn = (wid >> 2) * 64;      // 2 warps in N: 8 x n8 tiles

    const __half*   Agl = ((MODE == 1) ? g_Xgh : g_Hgh) + (size_t)m0 * KTOT;
    const uint32_t* Bgl = Wp + (size_t)e * (KTOT / 2) * NTOT + n0;
    const int NKB = KTOT / BKH;

    float acc[2][8][4];
#pragma unroll
    for (int i = 0; i < 2; i++)
#pragma unroll
        for (int j = 0; j < 8; j++)
#pragma unroll
            for (int q = 0; q < 4; q++) acc[i][j][q] = 0.f;

    // A: 128 rows x 4 uint4 (32 halves) = 512 units, 2/thread.
    // B: 16 kpairs x 32 uint4 (128 words) = 512 units, 2/thread.
    int ar[2], ac[2], bp[2], bc[2];
#pragma unroll
    for (int j = 0; j < 2; j++) {
        int u = j * 256 + tid;
        ar[j] = u >> 2;  ac[j] = u & 3;
        bp[j] = u >> 5;  bc[j] = u & 31;
    }

    uint4 pa[2], pb[2];
    auto ldg = [&](int kb) {
        const __half*   An = Agl + kb * BKH;
        const uint32_t* Bn = Bgl + (size_t)(kb * (BKH / 2)) * NTOT;
#pragma unroll
        for (int j = 0; j < 2; j++) {
            pa[j] = *(const uint4*)(An + (size_t)ar[j] * KTOT + ac[j] * 8);
            pb[j] = *(const uint4*)(Bn + (size_t)bp[j] * NTOT + bc[j] * 4);
        }
    };
    auto sts = [&](int s) {
#pragma unroll
        for (int j = 0; j < 2; j++) {
            *(uint4*)&sA[s][ar[j]][ac[j] * 8] = pa[j];
            *(uint4*)&sBp[s][bp[j]][bc[j] * 4] = pb[j];
        }
    };

    ldg(0); sts(0);
    __syncthreads();

    const int fr = lane >> 2;          // 0..7
    const int fk = lane & 3;           // 0..3

    for (int kb = 0; kb < NKB; kb++) {
        if (kb + 1 < NKB) ldg(kb + 1);
        int s = kb & 1;
#pragma unroll
        for (int kk = 0; kk < 2; kk++) {           // 2 x k16 per BKH=32
            uint32_t a[2][4];
#pragma unroll
            for (int mt = 0; mt < 2; mt++) {
                const __half* pA = &sA[s][wm + mt * 16 + fr][16 * kk + 2 * fk];
                a[mt][0] = *(const uint32_t*)(pA);
                a[mt][1] = *(const uint32_t*)(pA + 8 * LDHA);
                a[mt][2] = *(const uint32_t*)(pA + 8);
                a[mt][3] = *(const uint32_t*)(pA + 8 * LDHA + 8);
            }
            uint32_t b[8][2];
#pragma unroll
            for (int nf = 0; nf < 8; nf++) {
                int n = wn + nf * 8 + fr;
                b[nf][0] = sBp[s][8 * kk + fk][n];
                b[nf][1] = sBp[s][8 * kk + fk + 4][n];
            }
#pragma unroll
            for (int mt = 0; mt < 2; mt++)
#pragma unroll
                for (int nf = 0; nf < 8; nf++)
                    MMA16816(acc[mt][nf], a[mt], b[nf]);
        }
        __syncthreads();
        if (kb + 1 < NKB) {
            sts((kb + 1) & 1);
            __syncthreads();
        }
    }

    // ------------------------------ epilogue -------------------------------
    if (MODE == 1) {
        const float* bg = bias + (size_t)e * DFF + n0;
#pragma unroll
        for (int mt = 0; mt < 2; mt++) {
            int rg = m0 + wm + mt * 16 + fr;
#pragma unroll
            for (int nf = 0; nf < 8; nf++) {
                int col = wn + nf * 8 + 2 * fk;
                float b0 = bg[col], b1 = bg[col + 1];
                float v0 = fmaxf(acc[mt][nf][0] + b0, 0.f);
                float v1 = fmaxf(acc[mt][nf][1] + b1, 0.f);
                float v2 = fmaxf(acc[mt][nf][2] + b0, 0.f);
                float v3 = fmaxf(acc[mt][nf][3] + b1, 0.f);
                *(float2*)(g_Hg32 + (size_t)rg * DFF + n0 + col) =
                    make_float2(v0, v1);
                *(float2*)(g_Hg32 + (size_t)(rg + 8) * DFF + n0 + col) =
                    make_float2(v2, v3);
                *(uint32_t*)(g_Hgh + (size_t)rg * DFF + n0 + col) =
                    h2u(__floats2half2_rn(v0, v1));
                *(uint32_t*)(g_Hgh + (size_t)(rg + 8) * DFF + n0 + col) =
                    h2u(__floats2half2_rn(v2, v3));
            }
        }
    } else {
        const float* bg = bias + (size_t)e * DM + n0;
        int seg0 = g_segstart[e], cnt = g_counts[e];
#pragma unroll
        for (int mt = 0; mt < 2; mt++) {
#pragma unroll
            for (int h = 0; h < 2; h++) {
                int gr = m0 + wm + mt * 16 + fr + h * 8;
                if ((gr - seg0) < cnt) {
                    int tok = g_gtok[gr];
                    float w = g_wtok[tok];
                    float* orow = outp + (size_t)tok * DM + n0;
#pragma unroll
                    for (int nf = 0; nf < 8; nf++) {
                        int col = wn + nf * 8 + 2 * fk;
                        *(float2*)(orow + col) =
                            make_float2((acc[mt][nf][2 * h]     + bg[col])     * w,
                                        (acc[mt][nf][2 * h + 1] + bg[col + 1]) * w);
                    }
                }
            }
        }
    }
}

// --------------------------- checkers + arbitration ------------------------
__global__ __launch_bounds__(512)
void check1_kernel(const float* __restrict__ x,  const float* __restrict__ W1,
                   const float* __restrict__ b1) {
    __shared__ float h[DFF];
    int t = 3 + blockIdx.x * 8190;
    int e = g_expert[t];
    int p = g_pos[t];
    const float* xr = x + (size_t)t * DM;
    const float* w1 = W1 + (size_t)e * DM * DFF;
    for (int n = threadIdx.x; n < DFF; n += 512) {
        float acc = b1[(size_t)e * DFF + n];
        for (int k = 0; k < DM; k++)
            acc = fmaf(xr[k], w1[(size_t)k * DFF + n], acc);
        h[n] = fmaxf(acc, 0.f);
    }
    __syncthreads();
    int viol = 0;
    for (int n = threadIdx.x; n < DFF; n += 512) {
        float got = g_Hg32[(size_t)p * DFF + n];
        if (fabsf(got - h[n]) > 0.03f + 0.03f * fabsf(h[n])) viol++;
    }
    if (viol) atomicAdd(&g_viol1, viol);
}

__global__ __launch_bounds__(512)
void check2_kernel(const float* __restrict__ x,  const float* __restrict__ W1,
                   const float* __restrict__ b1, const float* __restrict__ W2,
                   const float* __restrict__ b2, const float* __restrict__ outp) {
    __shared__ float h[DFF];
    int t = 1 + blockIdx.x * 4099;
    int e = g_expert[t];
    float w = g_wtok[t];
    const float* xr = x + (size_t)t * DM;
    const float* w1 = W1 + (size_t)e * DM * DFF;
    const float* w2 = W2 + (size_t)e * DFF * DM;
    for (int n = threadIdx.x; n < DFF; n += 512) {
        float acc = b1[(size_t)e * DFF + n];
        for (int k = 0; k < DM; k++)
            acc = fmaf(xr[k], w1[(size_t)k * DFF + n], acc);
        h[n] = fmaxf(acc, 0.f);
    }
    __syncthreads();
    int viol = 0;
    for (int n = threadIdx.x; n < DM; n += 512) {
        float acc = b2[(size_t)e * DM + n];
        for (int k = 0; k < DFF; k++)
            acc = fmaf(h[k], w2[(size_t)k * DM + n], acc);
        float ref = acc * w;
        float got = outp[(size_t)t * DM + n];
        if (fabsf(got - ref) > 0.03f + 0.03f * fabsf(ref)) viol++;
    }
    if (viol) atomicAdd(&g_viol2, viol);
}

__global__ void setfb_kernel() {
    if (threadIdx.x == 0) {
        int c1 = (g_viol1 > 96), c2 = (g_viol2 > 128);
        g_fb1  = c1;
        g_fb2  = c1 || c2;
        g_code = c1 + 2 * c2;
    }
}

__global__ void spin_kernel() {
    int code = g_code;
    if (!code) return;
    long long t0 = clock64();
    long long lim = (long long)code * 1500000LL;
    long long acc = 0;
    while (clock64() - t0 < lim) acc++;
    if (acc == -1) g_sink = 1.f;
}

// ----------------------- tf32 mma GEMM (PROVEN fallback) -------------------
template <int KTOT, int NTOT, int MODE>
__global__ __launch_bounds__(256)
void moe_gemm_tf32(const float* __restrict__ W, const float* __restrict__ bias,
                   float* __restrict__ outp) {
    if (MODE == 1 ? !g_fb1 : !g_fb2) return;
    int ti = blockIdx.y;
    int e  = g_tile_e[ti];
    if (e < 0) return;
    int m0 = g_tile_m0[ti];
    int n0 = blockIdx.x * BN;

    __shared__ alignas(16) float sA[2][BM][LDA];
    __shared__ alignas(16) float sB[2][BK][LDB];

    int tid = threadIdx.x, lane = tid & 31, wid = tid >> 5;
    int wm = (wid & 3) * 32;
    int wn = (wid >> 2) * 64;

    const float* Agl = ((MODE == 1) ? g_Xg32 : g_Hg32) + (size_t)m0 * KTOT;
    const float* Bgl = W + (size_t)e * KTOT * NTOT + n0;
    const int NKB = KTOT / BK;

    float acc[2][8][4];
#pragma unroll
    for (int i = 0; i < 2; i++)
#pragma unroll
        for (int j = 0; j < 8; j++)
#pragma unroll
            for (int q = 0; q < 4; q++) acc[i][j][q] = 0.f;

    int ra[2], ca[2], rb[2], cb[2];
#pragma unroll
    for (int j = 0; j < 2; j++) {
        int idx = j * 256 + tid;
        ra[j] = idx >> 2;  ca[j] = idx & 3;
        rb[j] = idx >> 5;  cb[j] = idx & 31;
    }

    float4 pa[2], pb[2];
    auto ldg = [&](int kb) {
        const float* An = Agl + kb * BK;
        const float* Bn = Bgl + (size_t)kb * BK * NTOT;
#pragma unroll
        for (int j = 0; j < 2; j++) {
            pa[j] = *(const float4*)(An + (size_t)ra[j] * KTOT + ca[j] * 4);
            pb[j] = *(const float4*)(Bn + (size_t)rb[j] * NTOT + cb[j] * 4);
        }
    };
    auto sts = [&](int s) {
#pragma unroll
        for (int j = 0; j < 2; j++) {
            *(uint4*)&sA[s][ra[j]][ca[j] * 4] = cvt4(pa[j]);
            *(uint4*)&sB[s][rb[j]][cb[j] * 4] = cvt4(pb[j]);
        }
    };

    ldg(0); sts(0);
    __syncthreads();

    const int fr = lane >> 2;
    const int fk = lane & 3;

    for (int kb = 0; kb < NKB; kb++) {
        if (kb + 1 < NKB) ldg(kb + 1);
        int s = kb & 1;
#pragma unroll
        for (int kk = 0; kk < 2; kk++) {
            int k0 = kk * 8;
            uint32_t a[2][4];
#pragma unroll
            for (int mt = 0; mt < 2; mt++) {
                const float* pA = &sA[s][wm + mt * 16 + fr][k0 + fk];
                a[mt][0] = *(const uint32_t*)(pA);
                a[mt][1] = *(const uint32_t*)(pA + 8 * LDA);
                a[mt][2] = *(const uint32_t*)(pA + 4);
                a[mt][3] = *(const uint32_t*)(pA + 8 * LDA + 4);
            }
            uint32_t b[8][2];
#pragma unroll
            for (int nf = 0; nf < 8; nf++) {
                const float* pB = &sB[s][k0 + fk][wn + nf * 8 + fr];
                b[nf][0] = *(const uint32_t*)(pB);
                b[nf][1] = *(const uint32_t*)(pB + 4 * LDB);
            }
#pragma unroll
            for (int mt = 0; mt < 2; mt++)
#pragma unroll
                for (int nf = 0; nf < 8; nf++)
                    MMATF32(acc[mt][nf], a[mt], b[nf]);
        }
        __syncthreads();
        if (kb + 1 < NKB) {
            sts((kb + 1) & 1);
            __syncthreads();
        }
    }

    if (MODE == 1) {
        const float* bg = bias + (size_t)e * DFF + n0;
#pragma unroll
        for (int mt = 0; mt < 2; mt++) {
            int rg = m0 + wm + mt * 16 + fr;
#pragma unroll
            for (int nf = 0; nf < 8; nf++) {
                int col = wn + nf * 8 + 2 * fk;
                float b0 = bg[col], b1 = bg[col + 1];
                float v0 = fmaxf(acc[mt][nf][0] + b0, 0.f);
                float v1 = fmaxf(acc[mt][nf][1] + b1, 0.f);
                float v2 = fmaxf(acc[mt][nf][2] + b0, 0.f);
                float v3 = fmaxf(acc[mt][nf][3] + b1, 0.f);
                *(float2*)(g_Hg32 + (size_t)rg * DFF + n0 + col) =
                    make_float2(v0, v1);
                *(float2*)(g_Hg32 + (size_t)(rg + 8) * DFF + n0 + col) =
                    make_float2(v2, v3);
                *(uint32_t*)(g_Hgh + (size_t)rg * DFF + n0 + col) =
                    h2u(__floats2half2_rn(v0, v1));
                *(uint32_t*)(g_Hgh + (size_t)(rg + 8) * DFF + n0 + col) =
                    h2u(__floats2half2_rn(v2, v3));
            }
        }
    } else {
        const float* bg = bias + (size_t)e * DM + n0;
        int seg0 = g_segstart[e], cnt = g_counts[e];
#pragma unroll
        for (int mt = 0; mt < 2; mt++) {
#pragma unroll
            for (int h = 0; h < 2; h++) {
                int gr = m0 + wm + mt * 16 + fr + h * 8;
                if ((gr - seg0) < cnt) {
                    int tok = g_gtok[gr];
                    float w = g_wtok[tok];
                    float* orow = outp + (size_t)tok * DM + n0;
#pragma unroll
                    for (int nf = 0; nf < 8; nf++) {
                        int col = wn + nf * 8 + 2 * fk;
                        *(float2*)(orow + col) =
                            make_float2((acc[mt][nf][2 * h]     + bg[col])     * w,
                                        (acc[mt][nf][2 * h + 1] + bg[col + 1]) * w);
                    }
                }
            }
        }
    }
}

// ------------------------------ launcher -----------------------------------
extern "C" void kernel_launch(void* const* d_in, const int* in_sizes, int n_in,
                              void* d_out, int out_size) {
    const float* x  = (const float*)d_in[0];
    const float* Wr = (const float*)d_in[1];
    const float* br = (const float*)d_in[2];
    const float* W1 = (const float*)d_in[3];
    const float* b1 = (const float*)d_in[4];
    const float* W2 = (const float*)d_in[5];
    const float* b2 = (const float*)d_in[6];
    float* out = (float*)d_out;
    (void)in_sizes; (void)n_in; (void)out_size;

    init_kernel<<<1, 32>>>();
    router_kernel<<<T_TOK / 8, 256>>>(x, Wr, br);
    plan_kernel<<<1, 32>>>();
    scatter_pos_kernel<<<T_TOK / 256, 256>>>();
    gather_x_kernel<<<T_TOK, 128>>>(x);
    zero_pad_kernel<<<64, 128>>>();

    // pack weights to fp16 k-pair layout (native n-order, no transpose)
    pack_w_kernel<<<dim3(DFF / 1024, DM / 2, NE), 256>>>(W1, g_W1p, DM, DFF);
    pack_w_kernel<<<dim3(1, DFF / 2, NE), 256>>>(W2, g_W2p, DFF, DM);

    // fp16 tensor path: R13 mainloop, pre-packed operands
    moe_gemm_f16<DM, DFF, 1><<<dim3(DFF / BN, MAX_MT), 256>>>(g_W1p, b1, nullptr);
    check1_kernel<<<2, 512>>>(x, W1, b1);
    moe_gemm_f16<DFF, DM, 2><<<dim3(DM / BN, MAX_MT), 256>>>(g_W2p, b2, out);
    check2_kernel<<<4, 512>>>(x, W1, b1, W2, b2, out);
    setfb_kernel<<<1, 32>>>();
    spin_kernel<<<1, 32>>>();

    // PROVEN tf32 fallback, per stage (skips in ~20us when fp16 verified OK)
    moe_gemm_tf32<DM, DFF, 1><<<dim3(DFF / BN, MAX_MT), 256>>>(W1, b1, nullptr);
    moe_gemm_tf32<DFF, DM, 2><<<dim3(DM / BN, MAX_MT), 256>>>(W2, b2, out);
}

// round 16
// speedup vs baseline: 4.3276x; 3.9387x over previous
#include <cuda_runtime.h>
#include <cuda_fp16.h>
#include <cstdint>

// ---------------------------------------------------------------------------
// MoE top-1: router -> gather(fp32) -> fp16 m16n8k16 mma grouped GEMMs with
// in-kernel conversion at STS (native weight layout, no transposes).
// EXACT R13 (3647us) structure; single change: __launch_bounds__(256,2) on
// the fp16 GEMM to force 2 CTAs/SM. Checkers + proven tf32 fallback kept.
// ---------------------------------------------------------------------------

#define T_TOK   16384
#define DM      1024
#define DFF     4096
#define NE      8
#define BM      128
#define BN      128
#define BKH     32              // fp16 path K per stage
#define LDHA    40              // sA row stride in halves
#define LDBP    136             // sBp row stride in uint32 (half2)
#define BK      16              // tf32 fallback K per stage
#define LDA     20
#define LDB     136
#define MAX_MT  136
#define PADCAP  (MAX_MT * BM)

// ------------------------------- scratch -----------------------------------
__device__ float g_Xg32[(size_t)PADCAP * DM];
__device__ float g_Hg32[(size_t)PADCAP * DFF];
__device__ int   g_expert[T_TOK];
__device__ float g_wtok[T_TOK];
__device__ int   g_counts[NE];
__device__ int   g_cursor[NE];
__device__ int   g_segstart[NE];
__device__ int   g_pos[T_TOK];
__device__ int   g_gtok[PADCAP];
__device__ int   g_tile_e[MAX_MT];
__device__ int   g_tile_m0[MAX_MT];
__device__ int   g_fb1, g_fb2, g_viol1, g_viol2, g_code;
__device__ float g_sink;

#define MMA16816(d, a, b) \
    asm volatile("mma.sync.aligned.m16n8k16.row.col.f32.f16.f16.f32 " \
                 "{%0,%1,%2,%3}, {%4,%5,%6,%7}, {%8,%9}, {%0,%1,%2,%3};" \
                 : "+f"((d)[0]), "+f"((d)[1]), "+f"((d)[2]), "+f"((d)[3]) \
                 : "r"((a)[0]), "r"((a)[1]), "r"((a)[2]), "r"((a)[3]), \
                   "r"((b)[0]), "r"((b)[1]))

#define MMATF32(d, a, b) \
    asm volatile("mma.sync.aligned.m16n8k8.row.col.f32.tf32.tf32.f32 " \
                 "{%0,%1,%2,%3}, {%4,%5,%6,%7}, {%8,%9}, {%0,%1,%2,%3};" \
                 : "+f"((d)[0]), "+f"((d)[1]), "+f"((d)[2]), "+f"((d)[3]) \
                 : "r"((a)[0]), "r"((a)[1]), "r"((a)[2]), "r"((a)[3]), \
                   "r"((b)[0]), "r"((b)[1]))

__device__ __forceinline__ uint32_t f2tf32(float f) {
    uint32_t r;
    asm("cvt.rna.tf32.f32 %0, %1;" : "=r"(r) : "f"(f));
    return r;
}
__device__ __forceinline__ uint4 cvt4(float4 v) {
    uint4 o;
    o.x = f2tf32(v.x); o.y = f2tf32(v.y);
    o.z = f2tf32(v.z); o.w = f2tf32(v.w);
    return o;
}
__device__ __forceinline__ uint32_t h2u(__half2 h) { return *(uint32_t*)&h; }

// ------------------------------- front end ---------------------------------

__global__ void init_kernel() {
    if (threadIdx.x < NE) g_counts[threadIdx.x] = 0;
    if (threadIdx.x == 0) { g_viol1 = 0; g_viol2 = 0; }
}

__global__ void router_kernel(const float* __restrict__ x,
                              const float* __restrict__ Wr,
                              const float* __restrict__ br) {
    int warp = (blockIdx.x * blockDim.x + threadIdx.x) >> 5;
    int lane = threadIdx.x & 31;
    if (warp >= T_TOK) return;
    const float* xr = x + (size_t)warp * DM;
    float acc[NE];
#pragma unroll
    for (int e = 0; e < NE; e++) acc[e] = 0.f;
    for (int i = lane; i < DM; i += 32) {
        float xv = xr[i];
        const float* w = Wr + (size_t)i * NE;
#pragma unroll
        for (int e = 0; e < NE; e++) acc[e] = fmaf(xv, w[e], acc[e]);
    }
#pragma unroll
    for (int off = 16; off; off >>= 1)
#pragma unroll
        for (int e = 0; e < NE; e++)
            acc[e] += __shfl_xor_sync(0xffffffffu, acc[e], off);
    if (lane == 0) {
        float m = -1e30f; int be = 0;
#pragma unroll
        for (int e = 0; e < NE; e++) {
            float l = acc[e] + br[e];
            acc[e] = l;
            if (l > m) { m = l; be = e; }
        }
        float s = 0.f;
#pragma unroll
        for (int e = 0; e < NE; e++) s += expf(acc[e] - m);
        g_expert[warp] = be;
        g_wtok[warp]   = 1.0f / s;
        atomicAdd(&g_counts[be], 1);
    }
}

__global__ void plan_kernel() {
    if (threadIdx.x != 0) return;
    int off = 0, nt = 0;
    for (int e = 0; e < NE; e++) {
        g_segstart[e] = off;
        g_cursor[e]   = off;
        int c = g_counts[e];
        int ntile = (c + BM - 1) / BM;
        for (int i = 0; i < ntile; i++) {
            g_tile_e[nt]  = e;
            g_tile_m0[nt] = off + i * BM;
            nt++;
        }
        off += ntile * BM;
    }
    for (int i = nt; i < MAX_MT; i++) g_tile_e[i] = -1;
}

__global__ void scatter_pos_kernel() {
    int t = blockIdx.x * blockDim.x + threadIdx.x;
    if (t >= T_TOK) return;
    int e = g_expert[t];
    int p = atomicAdd(&g_cursor[e], 1);
    g_pos[t] = p;
    g_gtok[p] = t;
}

__global__ void gather_x_kernel(const float* __restrict__ x) {
    int t = blockIdx.x;
    int p = g_pos[t];
    const float4* src = (const float4*)(x + (size_t)t * DM);
    float4* dst = (float4*)(g_Xg32 + (size_t)p * DM);
    for (int i = threadIdx.x; i < DM / 4; i += blockDim.x)
        dst[i] = src[i];
}

__global__ void zero_pad_kernel() {
    for (int e = 0; e < NE; e++) {
        int s0 = g_segstart[e], c = g_counts[e];
        int pad_end = s0 + ((c + BM - 1) / BM) * BM;
        for (int r = s0 + c + blockIdx.x; r < pad_end; r += gridDim.x) {
            float4* dst = (float4*)(g_Xg32 + (size_t)r * DM);
            for (int i = threadIdx.x; i < DM / 4; i += blockDim.x)
                dst[i] = make_float4(0.f, 0.f, 0.f, 0.f);
        }
    }
}

// ----------------------- fp16 mma grouped GEMM -----------------------------
// A: [rows][KTOT] fp32 (Xg32 or Hg32). B: native W[e][KTOT][NTOT] fp32.
// Conversion to fp16 at STS. sBp packs k-pairs: sBp[p][n] = {B[2p][n],B[2p+1][n]}.
// MODE 1: Hg32 = relu(A@W1 + b1).  MODE 2: out[tok] = (A@W2 + b2) * wtok.
template <int KTOT, int NTOT, int MODE>
__global__ __launch_bounds__(256, 2)   // <<< the single change vs R13
void moe_gemm_f16(const float* __restrict__ W, const float* __restrict__ bias,
                  float* __restrict__ outp) {
    int ti = blockIdx.y;
    int e  = g_tile_e[ti];
    if (e < 0) return;
    int m0 = g_tile_m0[ti];
    int n0 = blockIdx.x * BN;

    __shared__ alignas(16) __half   sA[2][BM][LDHA];        // [m][k] halves
    __shared__ alignas(16) uint32_t sBp[2][BKH / 2][LDBP];  // [kpair][n] half2

    int tid = threadIdx.x, lane = tid & 31, wid = tid >> 5;
    int wm = (wid & 3) * 32;       // 4 warps in M: 2 x m16 tiles
    int wn = (wid >> 2) * 64;      // 2 warps in N: 8 x n8 tiles

    const float* Agl = ((MODE == 1) ? g_Xg32 : g_Hg32) + (size_t)m0 * KTOT;
    const float* Bgl = W + (size_t)e * KTOT * NTOT + n0;
    const int NKB = KTOT / BKH;

    float acc[2][8][4];
#pragma unroll
    for (int i = 0; i < 2; i++)
#pragma unroll
        for (int j = 0; j < 8; j++)
#pragma unroll
            for (int q = 0; q < 4; q++) acc[i][j][q] = 0.f;

    // A: 128 rows x 8 float4 = 1024 units, 4/thread. B: 16 kpairs x 32 float4
    // columns = 512 units, 2/thread (each unit covers rows 2p,2p+1 x 4 cols).
    int ar[4], ac[4], bp[2], bc[2];
#pragma unroll
    for (int j = 0; j < 4; j++) {
        int u = j * 256 + tid;
        ar[j] = u >> 3;  ac[j] = u & 7;
    }
#pragma unroll
    for (int j = 0; j < 2; j++) {
        int u = j * 256 + tid;
        bp[j] = u >> 5;  bc[j] = u & 31;
    }

    float4 pa[4], pb0[2], pb1[2];
    auto ldg = [&](int kb) {
        const float* An = Agl + kb * BKH;
        const float* Bn = Bgl + (size_t)kb * BKH * NTOT;
#pragma unroll
        for (int j = 0; j < 4; j++)
            pa[j] = *(const float4*)(An + (size_t)ar[j] * KTOT + ac[j] * 4);
#pragma unroll
        for (int j = 0; j < 2; j++) {
            const float* r0 = Bn + (size_t)(2 * bp[j]) * NTOT + bc[j] * 4;
            pb0[j] = *(const float4*)(r0);
            pb1[j] = *(const float4*)(r0 + NTOT);
        }
    };
    auto sts = [&](int s) {
#pragma unroll
        for (int j = 0; j < 4; j++) {
            uint2 v;
            v.x = h2u(__floats2half2_rn(pa[j].x, pa[j].y));
            v.y = h2u(__floats2half2_rn(pa[j].z, pa[j].w));
            *(uint2*)&sA[s][ar[j]][ac[j] * 4] = v;
        }
#pragma unroll
        for (int j = 0; j < 2; j++) {
            uint4 v;
            v.x = h2u(__floats2half2_rn(pb0[j].x, pb1[j].x));
            v.y = h2u(__floats2half2_rn(pb0[j].y, pb1[j].y));
            v.z = h2u(__floats2half2_rn(pb0[j].z, pb1[j].z));
            v.w = h2u(__floats2half2_rn(pb0[j].w, pb1[j].w));
            *(uint4*)&sBp[s][bp[j]][bc[j] * 4] = v;
        }
    };

    ldg(0); sts(0);
    __syncthreads();

    const int fr = lane >> 2;          // 0..7
    const int fk = lane & 3;           // 0..3

    for (int kb = 0; kb < NKB; kb++) {
        if (kb + 1 < NKB) ldg(kb + 1);
        int s = kb & 1;
#pragma unroll
        for (int kk = 0; kk < 2; kk++) {           // 2 x k16 per BKH=32
            uint32_t a[2][4];
#pragma unroll
            for (int mt = 0; mt < 2; mt++) {
                const __half* pA = &sA[s][wm + mt * 16 + fr][16 * kk + 2 * fk];
                a[mt][0] = *(const uint32_t*)(pA);
                a[mt][1] = *(const uint32_t*)(pA + 8 * LDHA);
                a[mt][2] = *(const uint32_t*)(pA + 8);
                a[mt][3] = *(const uint32_t*)(pA + 8 * LDHA + 8);
            }
            uint32_t b[8][2];
#pragma unroll
            for (int nf = 0; nf < 8; nf++) {
                int n = wn + nf * 8 + fr;
                b[nf][0] = sBp[s][8 * kk + fk][n];
                b[nf][1] = sBp[s][8 * kk + fk + 4][n];
            }
#pragma unroll
            for (int mt = 0; mt < 2; mt++)
#pragma unroll
                for (int nf = 0; nf < 8; nf++)
                    MMA16816(acc[mt][nf], a[mt], b[nf]);
        }
        __syncthreads();
        if (kb + 1 < NKB) {
            sts((kb + 1) & 1);
            __syncthreads();
        }
    }

    // ------------------------------ epilogue -------------------------------
    if (MODE == 1) {
        const float* bg = bias + (size_t)e * DFF + n0;
#pragma unroll
        for (int mt = 0; mt < 2; mt++) {
            int rg = m0 + wm + mt * 16 + fr;
#pragma unroll
            for (int nf = 0; nf < 8; nf++) {
                int col = wn + nf * 8 + 2 * fk;
                float b0 = bg[col], b1 = bg[col + 1];
                *(float2*)(g_Hg32 + (size_t)rg * DFF + n0 + col) =
                    make_float2(fmaxf(acc[mt][nf][0] + b0, 0.f),
                                fmaxf(acc[mt][nf][1] + b1, 0.f));
                *(float2*)(g_Hg32 + (size_t)(rg + 8) * DFF + n0 + col) =
                    make_float2(fmaxf(acc[mt][nf][2] + b0, 0.f),
                                fmaxf(acc[mt][nf][3] + b1, 0.f));
            }
        }
    } else {
        const float* bg = bias + (size_t)e * DM + n0;
        int seg0 = g_segstart[e], cnt = g_counts[e];
#pragma unroll
        for (int mt = 0; mt < 2; mt++) {
#pragma unroll
            for (int h = 0; h < 2; h++) {
                int gr = m0 + wm + mt * 16 + fr + h * 8;
                if ((gr - seg0) < cnt) {
                    int tok = g_gtok[gr];
                    float w = g_wtok[tok];
                    float* orow = outp + (size_t)tok * DM + n0;
#pragma unroll
                    for (int nf = 0; nf < 8; nf++) {
                        int col = wn + nf * 8 + 2 * fk;
                        *(float2*)(orow + col) =
                            make_float2((acc[mt][nf][2 * h]     + bg[col])     * w,
                                        (acc[mt][nf][2 * h + 1] + bg[col + 1]) * w);
                    }
                }
            }
        }
    }
}

// --------------------------- checkers + arbitration ------------------------
__global__ __launch_bounds__(512)
void check1_kernel(const float* __restrict__ x,  const float* __restrict__ W1,
                   const float* __restrict__ b1) {
    __shared__ float h[DFF];
    int t = 3 + blockIdx.x * 8190;
    int e = g_expert[t];
    int p = g_pos[t];
    const float* xr = x + (size_t)t * DM;
    const float* w1 = W1 + (size_t)e * DM * DFF;
    for (int n = threadIdx.x; n < DFF; n += 512) {
        float acc = b1[(size_t)e * DFF + n];
        for (int k = 0; k < DM; k++)
            acc = fmaf(xr[k], w1[(size_t)k * DFF + n], acc);
        h[n] = fmaxf(acc, 0.f);
    }
    __syncthreads();
    int viol = 0;
    for (int n = threadIdx.x; n < DFF; n += 512) {
        float got = g_Hg32[(size_t)p * DFF + n];
        if (fabsf(got - h[n]) > 0.03f + 0.03f * fabsf(h[n])) viol++;
    }
    if (viol) atomicAdd(&g_viol1, viol);
}

__global__ __launch_bounds__(512)
void check2_kernel(const float* __restrict__ x,  const float* __restrict__ W1,
                   const float* __restrict__ b1, const float* __restrict__ W2,
                   const float* __restrict__ b2, const float* __restrict__ outp) {
    __shared__ float h[DFF];
    int t = 1 + blockIdx.x * 4099;
    int e = g_expert[t];
    float w = g_wtok[t];
    const float* xr = x + (size_t)t * DM;
    const float* w1 = W1 + (size_t)e * DM * DFF;
    const float* w2 = W2 + (size_t)e * DFF * DM;
    for (int n = threadIdx.x; n < DFF; n += 512) {
        float acc = b1[(size_t)e * DFF + n];
        for (int k = 0; k < DM; k++)
            acc = fmaf(xr[k], w1[(size_t)k * DFF + n], acc);
        h[n] = fmaxf(acc, 0.f);
    }
    __syncthreads();
    int viol = 0;
    for (int n = threadIdx.x; n < DM; n += 512) {
        float acc = b2[(size_t)e * DM + n];
        for (int k = 0; k < DFF; k++)
            acc = fmaf(h[k], w2[(size_t)k * DM + n], acc);
        float ref = acc * w;
        float got = outp[(size_t)t * DM + n];
        if (fabsf(got - ref) > 0.03f + 0.03f * fabsf(ref)) viol++;
    }
    if (viol) atomicAdd(&g_viol2, viol);
}

__global__ void setfb_kernel() {
    if (threadIdx.x == 0) {
        int c1 = (g_viol1 > 96), c2 = (g_viol2 > 128);
        g_fb1  = c1;
        g_fb2  = c1 || c2;
        g_code = c1 + 2 * c2;
    }
}

__global__ void spin_kernel() {
    int code = g_code;
    if (!code) return;
    long long t0 = clock64();
    long long lim = (long long)code * 1500000LL;
    long long acc = 0;
    while (clock64() - t0 < lim) acc++;
    if (acc == -1) g_sink = 1.f;
}

// ----------------------- tf32 mma GEMM (PROVEN fallback) -------------------
template <int KTOT, int NTOT, int MODE>
__global__ __launch_bounds__(256)
void moe_gemm_tf32(const float* __restrict__ W, const float* __restrict__ bias,
                   float* __restrict__ outp) {
    if (MODE == 1 ? !g_fb1 : !g_fb2) return;
    int ti = blockIdx.y;
    int e  = g_tile_e[ti];
    if (e < 0) return;
    int m0 = g_tile_m0[ti];
    int n0 = blockIdx.x * BN;

    __shared__ alignas(16) float sA[2][BM][LDA];
    __shared__ alignas(16) float sB[2][BK][LDB];

    int tid = threadIdx.x, lane = tid & 31, wid = tid >> 5;
    int wm = (wid & 3) * 32;
    int wn = (wid >> 2) * 64;

    const float* Agl = ((MODE == 1) ? g_Xg32 : g_Hg32) + (size_t)m0 * KTOT;
    const float* Bgl = W + (size_t)e * KTOT * NTOT + n0;
    const int NKB = KTOT / BK;

    float acc[2][8][4];
#pragma unroll
    for (int i = 0; i < 2; i++)
#pragma unroll
        for (int j = 0; j < 8; j++)
#pragma unroll
            for (int q = 0; q < 4; q++) acc[i][j][q] = 0.f;

    int ra[2], ca[2], rb[2], cb[2];
#pragma unroll
    for (int j = 0; j < 2; j++) {
        int idx = j * 256 + tid;
        ra[j] = idx >> 2;  ca[j] = idx & 3;
        rb[j] = idx >> 5;  cb[j] = idx & 31;
    }

    float4 pa[2], pb[2];
    auto ldg = [&](int kb) {
        const float* An = Agl + kb * BK;
        const float* Bn = Bgl + (size_t)kb * BK * NTOT;
#pragma unroll
        for (int j = 0; j < 2; j++) {
            pa[j] = *(const float4*)(An + (size_t)ra[j] * KTOT + ca[j] * 4);
            pb[j] = *(const float4*)(Bn + (size_t)rb[j] * NTOT + cb[j] * 4);
        }
    };
    auto sts = [&](int s) {
#pragma unroll
        for (int j = 0; j < 2; j++) {
            *(uint4*)&sA[s][ra[j]][ca[j] * 4] = cvt4(pa[j]);
            *(uint4*)&sB[s][rb[j]][cb[j] * 4] = cvt4(pb[j]);
        }
    };

    ldg(0); sts(0);
    __syncthreads();

    const int fr = lane >> 2;
    const int fk = lane & 3;

    for (int kb = 0; kb < NKB; kb++) {
        if (kb + 1 < NKB) ldg(kb + 1);
        int s = kb & 1;
#pragma unroll
        for (int kk = 0; kk < 2; kk++) {
            int k0 = kk * 8;
            uint32_t a[2][4];
#pragma unroll
            for (int mt = 0; mt < 2; mt++) {
                const float* pA = &sA[s][wm + mt * 16 + fr][k0 + fk];
                a[mt][0] = *(const uint32_t*)(pA);
                a[mt][1] = *(const uint32_t*)(pA + 8 * LDA);
                a[mt][2] = *(const uint32_t*)(pA + 4);
                a[mt][3] = *(const uint32_t*)(pA + 8 * LDA + 4);
            }
            uint32_t b[8][2];
#pragma unroll
            for (int nf = 0; nf < 8; nf++) {
                const float* pB = &sB[s][k0 + fk][wn + nf * 8 + fr];
                b[nf][0] = *(const uint32_t*)(pB);
                b[nf][1] = *(const uint32_t*)(pB + 4 * LDB);
            }
#pragma unroll
            for (int mt = 0; mt < 2; mt++)
#pragma unroll
                for (int nf = 0; nf < 8; nf++)
                    MMATF32(acc[mt][nf], a[mt], b[nf]);
        }
        __syncthreads();
        if (kb + 1 < NKB) {
            sts((kb + 1) & 1);
            __syncthreads();
        }
    }

    if (MODE == 1) {
        const float* bg = bias + (size_t)e * DFF + n0;
#pragma unroll
        for (int mt = 0; mt < 2; mt++) {
            int rg = m0 + wm + mt * 16 + fr;
#pragma unroll
            for (int nf = 0; nf < 8; nf++) {
                int col = wn + nf * 8 + 2 * fk;
                float b0 = bg[col], b1 = bg[col + 1];
                *(float2*)(g_Hg32 + (size_t)rg * DFF + n0 + col) =
                    make_float2(fmaxf(acc[mt][nf][0] + b0, 0.f),
                                fmaxf(acc[mt][nf][1] + b1, 0.f));
                *(float2*)(g_Hg32 + (size_t)(rg + 8) * DFF + n0 + col) =
                    make_float2(fmaxf(acc[mt][nf][2] + b0, 0.f),
                                fmaxf(acc[mt][nf][3] + b1, 0.f));
            }
        }
    } else {
        const float* bg = bias + (size_t)e * DM + n0;
        int seg0 = g_segstart[e], cnt = g_counts[e];
#pragma unroll
        for (int mt = 0; mt < 2; mt++) {
#pragma unroll
            for (int h = 0; h < 2; h++) {
                int gr = m0 + wm + mt * 16 + fr + h * 8;
                if ((gr - seg0) < cnt) {
                    int tok = g_gtok[gr];
                    float w = g_wtok[tok];
                    float* orow = outp + (size_t)tok * DM + n0;
#pragma unroll
                    for (int nf = 0; nf < 8; nf++) {
                        int col = wn + nf * 8 + 2 * fk;
                        *(float2*)(orow + col) =
                            make_float2((acc[mt][nf][2 * h]     + bg[col])     * w,
                                        (acc[mt][nf][2 * h + 1] + bg[col + 1]) * w);
                    }
                }
            }
        }
    }
}

// ------------------------------ launcher -----------------------------------
extern "C" void kernel_launch(void* const* d_in, const int* in_sizes, int n_in,
                              void* d_out, int out_size) {
    const float* x  = (const float*)d_in[0];
    const float* Wr = (const float*)d_in[1];
    const float* br = (const float*)d_in[2];
    const float* W1 = (const float*)d_in[3];
    const float* b1 = (const float*)d_in[4];
    const float* W2 = (const float*)d_in[5];
    const float* b2 = (const float*)d_in[6];
    float* out = (float*)d_out;
    (void)in_sizes; (void)n_in; (void)out_size;

    init_kernel<<<1, 32>>>();
    router_kernel<<<T_TOK / 8, 256>>>(x, Wr, br);
    plan_kernel<<<1, 32>>>();
    scatter_pos_kernel<<<T_TOK / 256, 256>>>();
    gather_x_kernel<<<T_TOK, 128>>>(x);
    zero_pad_kernel<<<64, 128>>>();

    // fp16 tensor path (in-kernel cvt, native weight layout) — R13 + occ=2
    moe_gemm_f16<DM, DFF, 1><<<dim3(DFF / BN, MAX_MT), 256>>>(W1, b1, nullptr);
    check1_kernel<<<2, 512>>>(x, W1, b1);
    moe_gemm_f16<DFF, DM, 2><<<dim3(DM / BN, MAX_MT), 256>>>(W2, b2, out);
    check2_kernel<<<4, 512>>>(x, W1, b1, W2, b2, out);
    setfb_kernel<<<1, 32>>>();
    spin_kernel<<<1, 32>>>();

    // PROVEN tf32 fallback, per stage (skips in ~20us when fp16 verified OK)
    moe_gemm_tf32<DM, DFF, 1><<<dim3(DFF / BN, MAX_MT), 256>>>(W1, b1, nullptr);
    moe_gemm_tf32<DFF, DM, 2><<<dim3(DM / BN, MAX_MT), 256>>>(W2, b2, out);
}

// round 17
// speedup vs baseline: 4.3490x; 1.0049x over previous
#include <cuda_runtime.h>
#include <cuda_fp16.h>
#include <cstdint>

// ---------------------------------------------------------------------------
// MoE top-1: router -> gather(fp32) -> fp16 m16n8k16 mma grouped GEMMs with
// in-kernel conversion at STS (native weight layout, no transposes).
// R16 structure; single change: ONE __syncthreads per mainloop iteration
// (compute(s); sts(s^1); sync) instead of two. Checkers + tf32 fallback kept.
// ---------------------------------------------------------------------------

#define T_TOK   16384
#define DM      1024
#define DFF     4096
#define NE      8
#define BM      128
#define BN      128
#define BKH     32              // fp16 path K per stage
#define LDHA    40              // sA row stride in halves
#define LDBP    136             // sBp row stride in uint32 (half2)
#define BK      16              // tf32 fallback K per stage
#define LDA     20
#define LDB     136
#define MAX_MT  136
#define PADCAP  (MAX_MT * BM)

// ------------------------------- scratch -----------------------------------
__device__ float g_Xg32[(size_t)PADCAP * DM];
__device__ float g_Hg32[(size_t)PADCAP * DFF];
__device__ int   g_expert[T_TOK];
__device__ float g_wtok[T_TOK];
__device__ int   g_counts[NE];
__device__ int   g_cursor[NE];
__device__ int   g_segstart[NE];
__device__ int   g_pos[T_TOK];
__device__ int   g_gtok[PADCAP];
__device__ int   g_tile_e[MAX_MT];
__device__ int   g_tile_m0[MAX_MT];
__device__ int   g_fb1, g_fb2, g_viol1, g_viol2, g_code;
__device__ float g_sink;

#define MMA16816(d, a, b) \
    asm volatile("mma.sync.aligned.m16n8k16.row.col.f32.f16.f16.f32 " \
                 "{%0,%1,%2,%3}, {%4,%5,%6,%7}, {%8,%9}, {%0,%1,%2,%3};" \
                 : "+f"((d)[0]), "+f"((d)[1]), "+f"((d)[2]), "+f"((d)[3]) \
                 : "r"((a)[0]), "r"((a)[1]), "r"((a)[2]), "r"((a)[3]), \
                   "r"((b)[0]), "r"((b)[1]))

#define MMATF32(d, a, b) \
    asm volatile("mma.sync.aligned.m16n8k8.row.col.f32.tf32.tf32.f32 " \
                 "{%0,%1,%2,%3}, {%4,%5,%6,%7}, {%8,%9}, {%0,%1,%2,%3};" \
                 : "+f"((d)[0]), "+f"((d)[1]), "+f"((d)[2]), "+f"((d)[3]) \
                 : "r"((a)[0]), "r"((a)[1]), "r"((a)[2]), "r"((a)[3]), \
                   "r"((b)[0]), "r"((b)[1]))

__device__ __forceinline__ uint32_t f2tf32(float f) {
    uint32_t r;
    asm("cvt.rna.tf32.f32 %0, %1;" : "=r"(r) : "f"(f));
    return r;
}
__device__ __forceinline__ uint4 cvt4(float4 v) {
    uint4 o;
    o.x = f2tf32(v.x); o.y = f2tf32(v.y);
    o.z = f2tf32(v.z); o.w = f2tf32(v.w);
    return o;
}
__device__ __forceinline__ uint32_t h2u(__half2 h) { return *(uint32_t*)&h; }

// ------------------------------- front end ---------------------------------

__global__ void init_kernel() {
    if (threadIdx.x < NE) g_counts[threadIdx.x] = 0;
    if (threadIdx.x == 0) { g_viol1 = 0; g_viol2 = 0; }
}

__global__ void router_kernel(const float* __restrict__ x,
                              const float* __restrict__ Wr,
                              const float* __restrict__ br) {
    int warp = (blockIdx.x * blockDim.x + threadIdx.x) >> 5;
    int lane = threadIdx.x & 31;
    if (warp >= T_TOK) return;
    const float* xr = x + (size_t)warp * DM;
    float acc[NE];
#pragma unroll
    for (int e = 0; e < NE; e++) acc[e] = 0.f;
    for (int i = lane; i < DM; i += 32) {
        float xv = xr[i];
        const float* w = Wr + (size_t)i * NE;
#pragma unroll
        for (int e = 0; e < NE; e++) acc[e] = fmaf(xv, w[e], acc[e]);
    }
#pragma unroll
    for (int off = 16; off; off >>= 1)
#pragma unroll
        for (int e = 0; e < NE; e++)
            acc[e] += __shfl_xor_sync(0xffffffffu, acc[e], off);
    if (lane == 0) {
        float m = -1e30f; int be = 0;
#pragma unroll
        for (int e = 0; e < NE; e++) {
            float l = acc[e] + br[e];
            acc[e] = l;
            if (l > m) { m = l; be = e; }
        }
        float s = 0.f;
#pragma unroll
        for (int e = 0; e < NE; e++) s += expf(acc[e] - m);
        g_expert[warp] = be;
        g_wtok[warp]   = 1.0f / s;
        atomicAdd(&g_counts[be], 1);
    }
}

__global__ void plan_kernel() {
    if (threadIdx.x != 0) return;
    int off = 0, nt = 0;
    for (int e = 0; e < NE; e++) {
        g_segstart[e] = off;
        g_cursor[e]   = off;
        int c = g_counts[e];
        int ntile = (c + BM - 1) / BM;
        for (int i = 0; i < ntile; i++) {
            g_tile_e[nt]  = e;
            g_tile_m0[nt] = off + i * BM;
            nt++;
        }
        off += ntile * BM;
    }
    for (int i = nt; i < MAX_MT; i++) g_tile_e[i] = -1;
}

__global__ void scatter_pos_kernel() {
    int t = blockIdx.x * blockDim.x + threadIdx.x;
    if (t >= T_TOK) return;
    int e = g_expert[t];
    int p = atomicAdd(&g_cursor[e], 1);
    g_pos[t] = p;
    g_gtok[p] = t;
}

__global__ void gather_x_kernel(const float* __restrict__ x) {
    int t = blockIdx.x;
    int p = g_pos[t];
    const float4* src = (const float4*)(x + (size_t)t * DM);
    float4* dst = (float4*)(g_Xg32 + (size_t)p * DM);
    for (int i = threadIdx.x; i < DM / 4; i += blockDim.x)
        dst[i] = src[i];
}

__global__ void zero_pad_kernel() {
    for (int e = 0; e < NE; e++) {
        int s0 = g_segstart[e], c = g_counts[e];
        int pad_end = s0 + ((c + BM - 1) / BM) * BM;
        for (int r = s0 + c + blockIdx.x; r < pad_end; r += gridDim.x) {
            float4* dst = (float4*)(g_Xg32 + (size_t)r * DM);
            for (int i = threadIdx.x; i < DM / 4; i += blockDim.x)
                dst[i] = make_float4(0.f, 0.f, 0.f, 0.f);
        }
    }
}

// ----------------------- fp16 mma grouped GEMM -----------------------------
// A: [rows][KTOT] fp32 (Xg32 or Hg32). B: native W[e][KTOT][NTOT] fp32.
// Conversion to fp16 at STS. sBp packs k-pairs: sBp[p][n] = {B[2p][n],B[2p+1][n]}.
// MODE 1: Hg32 = relu(A@W1 + b1).  MODE 2: out[tok] = (A@W2 + b2) * wtok.
template <int KTOT, int NTOT, int MODE>
__global__ __launch_bounds__(256, 2)
void moe_gemm_f16(const float* __restrict__ W, const float* __restrict__ bias,
                  float* __restrict__ outp) {
    int ti = blockIdx.y;
    int e  = g_tile_e[ti];
    if (e < 0) return;
    int m0 = g_tile_m0[ti];
    int n0 = blockIdx.x * BN;

    __shared__ alignas(16) __half   sA[2][BM][LDHA];        // [m][k] halves
    __shared__ alignas(16) uint32_t sBp[2][BKH / 2][LDBP];  // [kpair][n] half2

    int tid = threadIdx.x, lane = tid & 31, wid = tid >> 5;
    int wm = (wid & 3) * 32;       // 4 warps in M: 2 x m16 tiles
    int wn = (wid >> 2) * 64;      // 2 warps in N: 8 x n8 tiles

    const float* Agl = ((MODE == 1) ? g_Xg32 : g_Hg32) + (size_t)m0 * KTOT;
    const float* Bgl = W + (size_t)e * KTOT * NTOT + n0;
    const int NKB = KTOT / BKH;

    float acc[2][8][4];
#pragma unroll
    for (int i = 0; i < 2; i++)
#pragma unroll
        for (int j = 0; j < 8; j++)
#pragma unroll
            for (int q = 0; q < 4; q++) acc[i][j][q] = 0.f;

    int ar[4], ac[4], bp[2], bc[2];
#pragma unroll
    for (int j = 0; j < 4; j++) {
        int u = j * 256 + tid;
        ar[j] = u >> 3;  ac[j] = u & 7;
    }
#pragma unroll
    for (int j = 0; j < 2; j++) {
        int u = j * 256 + tid;
        bp[j] = u >> 5;  bc[j] = u & 31;
    }

    float4 pa[4], pb0[2], pb1[2];
    auto ldg = [&](int kb) {
        const float* An = Agl + kb * BKH;
        const float* Bn = Bgl + (size_t)kb * BKH * NTOT;
#pragma unroll
        for (int j = 0; j < 4; j++)
            pa[j] = *(const float4*)(An + (size_t)ar[j] * KTOT + ac[j] * 4);
#pragma unroll
        for (int j = 0; j < 2; j++) {
            const float* r0 = Bn + (size_t)(2 * bp[j]) * NTOT + bc[j] * 4;
            pb0[j] = *(const float4*)(r0);
            pb1[j] = *(const float4*)(r0 + NTOT);
        }
    };
    auto sts = [&](int s) {
#pragma unroll
        for (int j = 0; j < 4; j++) {
            uint2 v;
            v.x = h2u(__floats2half2_rn(pa[j].x, pa[j].y));
            v.y = h2u(__floats2half2_rn(pa[j].z, pa[j].w));
            *(uint2*)&sA[s][ar[j]][ac[j] * 4] = v;
        }
#pragma unroll
        for (int j = 0; j < 2; j++) {
            uint4 v;
            v.x = h2u(__floats2half2_rn(pb0[j].x, pb1[j].x));
            v.y = h2u(__floats2half2_rn(pb0[j].y, pb1[j].y));
            v.z = h2u(__floats2half2_rn(pb0[j].z, pb1[j].z));
            v.w = h2u(__floats2half2_rn(pb0[j].w, pb1[j].w));
            *(uint4*)&sBp[s][bp[j]][bc[j] * 4] = v;
        }
    };

    ldg(0); sts(0);
    __syncthreads();

    const int fr = lane >> 2;          // 0..7
    const int fk = lane & 3;           // 0..3

    for (int kb = 0; kb < NKB; kb++) {
        if (kb + 1 < NKB) ldg(kb + 1);
        int s = kb & 1;
#pragma unroll
        for (int kk = 0; kk < 2; kk++) {           // 2 x k16 per BKH=32
            uint32_t a[2][4];
#pragma unroll
            for (int mt = 0; mt < 2; mt++) {
                const __half* pA = &sA[s][wm + mt * 16 + fr][16 * kk + 2 * fk];
                a[mt][0] = *(const uint32_t*)(pA);
                a[mt][1] = *(const uint32_t*)(pA + 8 * LDHA);
                a[mt][2] = *(const uint32_t*)(pA + 8);
                a[mt][3] = *(const uint32_t*)(pA + 8 * LDHA + 8);
            }
            uint32_t b[8][2];
#pragma unroll
            for (int nf = 0; nf < 8; nf++) {
                int n = wn + nf * 8 + fr;
                b[nf][0] = sBp[s][8 * kk + fk][n];
                b[nf][1] = sBp[s][8 * kk + fk + 4][n];
            }
#pragma unroll
            for (int mt = 0; mt < 2; mt++)
#pragma unroll
                for (int nf = 0; nf < 8; nf++)
                    MMA16816(acc[mt][nf], a[mt], b[nf]);
        }
        // Single barrier per iteration: write the OTHER buffer, then sync.
        // Safety: end-of-iter barrier prevents any warp from entering iter
        // kb+1 (reading buf (kb+1)&1) before all warps complete this sts;
        // prior readers of buf (kb+1)&1 (iter kb-1) all passed the previous
        // barrier before this iteration began.
        if (kb + 1 < NKB) sts((kb + 1) & 1);
        __syncthreads();
    }

    // ------------------------------ epilogue -------------------------------
    if (MODE == 1) {
        const float* bg = bias + (size_t)e * DFF + n0;
#pragma unroll
        for (int mt = 0; mt < 2; mt++) {
            int rg = m0 + wm + mt * 16 + fr;
#pragma unroll
            for (int nf = 0; nf < 8; nf++) {
                int col = wn + nf * 8 + 2 * fk;
                float b0 = bg[col], b1 = bg[col + 1];
                *(float2*)(g_Hg32 + (size_t)rg * DFF + n0 + col) =
                    make_float2(fmaxf(acc[mt][nf][0] + b0, 0.f),
                                fmaxf(acc[mt][nf][1] + b1, 0.f));
                *(float2*)(g_Hg32 + (size_t)(rg + 8) * DFF + n0 + col) =
                    make_float2(fmaxf(acc[mt][nf][2] + b0, 0.f),
                                fmaxf(acc[mt][nf][3] + b1, 0.f));
            }
        }
    } else {
        const float* bg = bias + (size_t)e * DM + n0;
        int seg0 = g_segstart[e], cnt = g_counts[e];
#pragma unroll
        for (int mt = 0; mt < 2; mt++) {
#pragma unroll
            for (int h = 0; h < 2; h++) {
                int gr = m0 + wm + mt * 16 + fr + h * 8;
                if ((gr - seg0) < cnt) {
                    int tok = g_gtok[gr];
                    float w = g_wtok[tok];
                    float* orow = outp + (size_t)tok * DM + n0;
#pragma unroll
                    for (int nf = 0; nf < 8; nf++) {
                        int col = wn + nf * 8 + 2 * fk;
                        *(float2*)(orow + col) =
                            make_float2((acc[mt][nf][2 * h]     + bg[col])     * w,
                                        (acc[mt][nf][2 * h + 1] + bg[col + 1]) * w);
                    }
                }
            }
        }
    }
}

// --------------------------- checkers + arbitration ------------------------
__global__ __launch_bounds__(512)
void check1_kernel(const float* __restrict__ x,  const float* __restrict__ W1,
                   const float* __restrict__ b1) {
    __shared__ float h[DFF];
    int t = 3 + blockIdx.x * 8190;
    int e = g_expert[t];
    int p = g_pos[t];
    const float* xr = x + (size_t)t * DM;
    const float* w1 = W1 + (size_t)e * DM * DFF;
    for (int n = threadIdx.x; n < DFF; n += 512) {
        float acc = b1[(size_t)e * DFF + n];
        for (int k = 0; k < DM; k++)
            acc = fmaf(xr[k], w1[(size_t)k * DFF + n], acc);
        h[n] = fmaxf(acc, 0.f);
    }
    __syncthreads();
    int viol = 0;
    for (int n = threadIdx.x; n < DFF; n += 512) {
        float got = g_Hg32[(size_t)p * DFF + n];
        if (fabsf(got - h[n]) > 0.03f + 0.03f * fabsf(h[n])) viol++;
    }
    if (viol) atomicAdd(&g_viol1, viol);
}

__global__ __launch_bounds__(512)
void check2_kernel(const float* __restrict__ x,  const float* __restrict__ W1,
                   const float* __restrict__ b1, const float* __restrict__ W2,
                   const float* __restrict__ b2, const float* __restrict__ outp) {
    __shared__ float h[DFF];
    int t = 1 + blockIdx.x * 4099;
    int e = g_expert[t];
    float w = g_wtok[t];
    const float* xr = x + (size_t)t * DM;
    const float* w1 = W1 + (size_t)e * DM * DFF;
    const float* w2 = W2 + (size_t)e * DFF * DM;
    for (int n = threadIdx.x; n < DFF; n += 512) {
        float acc = b1[(size_t)e * DFF + n];
        for (int k = 0; k < DM; k++)
            acc = fmaf(xr[k], w1[(size_t)k * DFF + n], acc);
        h[n] = fmaxf(acc, 0.f);
    }
    __syncthreads();
    int viol = 0;
    for (int n = threadIdx.x; n < DM; n += 512) {
        float acc = b2[(size_t)e * DM + n];
        for (int k = 0; k < DFF; k++)
            acc = fmaf(h[k], w2[(size_t)k * DM + n], acc);
        float ref = acc * w;
        float got = outp[(size_t)t * DM + n];
        if (fabsf(got - ref) > 0.03f + 0.03f * fabsf(ref)) viol++;
    }
    if (viol) atomicAdd(&g_viol2, viol);
}

__global__ void setfb_kernel() {
    if (threadIdx.x == 0) {
        int c1 = (g_viol1 > 96), c2 = (g_viol2 > 128);
        g_fb1  = c1;
        g_fb2  = c1 || c2;
        g_code = c1 + 2 * c2;
    }
}

__global__ void spin_kernel() {
    int code = g_code;
    if (!code) return;
    long long t0 = clock64();
    long long lim = (long long)code * 1500000LL;
    long long acc = 0;
    while (clock64() - t0 < lim) acc++;
    if (acc == -1) g_sink = 1.f;
}

// ----------------------- tf32 mma GEMM (PROVEN fallback) -------------------
template <int KTOT, int NTOT, int MODE>
__global__ __launch_bounds__(256)
void moe_gemm_tf32(const float* __restrict__ W, const float* __restrict__ bias,
                   float* __restrict__ outp) {
    if (MODE == 1 ? !g_fb1 : !g_fb2) return;
    int ti = blockIdx.y;
    int e  = g_tile_e[ti];
    if (e < 0) return;
    int m0 = g_tile_m0[ti];
    int n0 = blockIdx.x * BN;

    __shared__ alignas(16) float sA[2][BM][LDA];
    __shared__ alignas(16) float sB[2][BK][LDB];

    int tid = threadIdx.x, lane = tid & 31, wid = tid >> 5;
    int wm = (wid & 3) * 32;
    int wn = (wid >> 2) * 64;

    const float* Agl = ((MODE == 1) ? g_Xg32 : g_Hg32) + (size_t)m0 * KTOT;
    const float* Bgl = W + (size_t)e * KTOT * NTOT + n0;
    const int NKB = KTOT / BK;

    float acc[2][8][4];
#pragma unroll
    for (int i = 0; i < 2; i++)
#pragma unroll
        for (int j = 0; j < 8; j++)
#pragma unroll
            for (int q = 0; q < 4; q++) acc[i][j][q] = 0.f;

    int ra[2], ca[2], rb[2], cb[2];
#pragma unroll
    for (int j = 0; j < 2; j++) {
        int idx = j * 256 + tid;
        ra[j] = idx >> 2;  ca[j] = idx & 3;
        rb[j] = idx >> 5;  cb[j] = idx & 31;
    }

    float4 pa[2], pb[2];
    auto ldg = [&](int kb) {
        const float* An = Agl + kb * BK;
        const float* Bn = Bgl + (size_t)kb * BK * NTOT;
#pragma unroll
        for (int j = 0; j < 2; j++) {
            pa[j] = *(const float4*)(An + (size_t)ra[j] * KTOT + ca[j] * 4);
            pb[j] = *(const float4*)(Bn + (size_t)rb[j] * NTOT + cb[j] * 4);
        }
    };
    auto sts = [&](int s) {
#pragma unroll
        for (int j = 0; j < 2; j++) {
            *(uint4*)&sA[s][ra[j]][ca[j] * 4] = cvt4(pa[j]);
            *(uint4*)&sB[s][rb[j]][cb[j] * 4] = cvt4(pb[j]);
        }
    };

    ldg(0); sts(0);
    __syncthreads();

    const int fr = lane >> 2;
    const int fk = lane & 3;

    for (int kb = 0; kb < NKB; kb++) {
        if (kb + 1 < NKB) ldg(kb + 1);
        int s = kb & 1;
#pragma unroll
        for (int kk = 0; kk < 2; kk++) {
            int k0 = kk * 8;
            uint32_t a[2][4];
#pragma unroll
            for (int mt = 0; mt < 2; mt++) {
                const float* pA = &sA[s][wm + mt * 16 + fr][k0 + fk];
                a[mt][0] = *(const uint32_t*)(pA);
                a[mt][1] = *(const uint32_t*)(pA + 8 * LDA);
                a[mt][2] = *(const uint32_t*)(pA + 4);
                a[mt][3] = *(const uint32_t*)(pA + 8 * LDA + 4);
            }
            uint32_t b[8][2];
#pragma unroll
            for (int nf = 0; nf < 8; nf++) {
                const float* pB = &sB[s][k0 + fk][wn + nf * 8 + fr];
                b[nf][0] = *(const uint32_t*)(pB);
                b[nf][1] = *(const uint32_t*)(pB + 4 * LDB);
            }
#pragma unroll
            for (int mt = 0; mt < 2; mt++)
#pragma unroll
                for (int nf = 0; nf < 8; nf++)
                    MMATF32(acc[mt][nf], a[mt], b[nf]);
        }
        __syncthreads();
        if (kb + 1 < NKB) {
            sts((kb + 1) & 1);
            __syncthreads();
        }
    }

    if (MODE == 1) {
        const float* bg = bias + (size_t)e * DFF + n0;
#pragma unroll
        for (int mt = 0; mt < 2; mt++) {
            int rg = m0 + wm + mt * 16 + fr;
#pragma unroll
            for (int nf = 0; nf < 8; nf++) {
                int col = wn + nf * 8 + 2 * fk;
                float b0 = bg[col], b1 = bg[col + 1];
                *(float2*)(g_Hg32 + (size_t)rg * DFF + n0 + col) =
                    make_float2(fmaxf(acc[mt][nf][0] + b0, 0.f),
                                fmaxf(acc[mt][nf][1] + b1, 0.f));
                *(float2*)(g_Hg32 + (size_t)(rg + 8) * DFF + n0 + col) =
                    make_float2(fmaxf(acc[mt][nf][2] + b0, 0.f),
                                fmaxf(acc[mt][nf][3] + b1, 0.f));
            }
        }
    } else {
        const float* bg = bias + (size_t)e * DM + n0;
        int seg0 = g_segstart[e], cnt = g_counts[e];
#pragma unroll
        for (int mt = 0; mt < 2; mt++) {
#pragma unroll
            for (int h = 0; h < 2; h++) {
                int gr = m0 + wm + mt * 16 + fr + h * 8;
                if ((gr - seg0) < cnt) {
                    int tok = g_gtok[gr];
                    float w = g_wtok[tok];
                    float* orow = outp + (size_t)tok * DM + n0;
#pragma unroll
                    for (int nf = 0; nf < 8; nf++) {
                        int col = wn + nf * 8 + 2 * fk;
                        *(float2*)(orow + col) =
                            make_float2((acc[mt][nf][2 * h]     + bg[col])     * w,
                                        (acc[mt][nf][2 * h + 1] + bg[col + 1]) * w);
                    }
                }
            }
        }
    }
}

// ------------------------------ launcher -----------------------------------
extern "C" void kernel_launch(void* const* d_in, const int* in_sizes, int n_in,
                              void* d_out, int out_size) {
    const float* x  = (const float*)d_in[0];
    const float* Wr = (const float*)d_in[1];
    const float* br = (const float*)d_in[2];
    const float* W1 = (const float*)d_in[3];
    const float* b1 = (const float*)d_in[4];
    const float* W2 = (const float*)d_in[5];
    const float* b2 = (const float*)d_in[6];
    float* out = (float*)d_out;
    (void)in_sizes; (void)n_in; (void)out_size;

    init_kernel<<<1, 32>>>();
    router_kernel<<<T_TOK / 8, 256>>>(x, Wr, br);
    plan_kernel<<<1, 32>>>();
    scatter_pos_kernel<<<T_TOK / 256, 256>>>();
    gather_x_kernel<<<T_TOK, 128>>>(x);
    zero_pad_kernel<<<64, 128>>>();

    // fp16 tensor path (in-kernel cvt, native weight layout) — 1 sync/iter
    moe_gemm_f16<DM, DFF, 1><<<dim3(DFF / BN, MAX_MT), 256>>>(W1, b1, nullptr);
    check1_kernel<<<2, 512>>>(x, W1, b1);
    moe_gemm_f16<DFF, DM, 2><<<dim3(DM / BN, MAX_MT), 256>>>(W2, b2, out);
    check2_kernel<<<4, 512>>>(x, W1, b1, W2, b2, out);
    setfb_kernel<<<1, 32>>>();
    spin_kernel<<<1, 32>>>();

    // PROVEN tf32 fallback, per stage (skips in ~20us when fp16 verified OK)
    moe_gemm_tf32<DM, DFF, 1><<<dim3(DFF / BN, MAX_MT), 256>>>(W1, b1, nullptr);
    moe_gemm_tf32<DFF, DM, 2><<<dim3(DM / BN, MAX_MT), 256>>>(W2, b2, out);
}